// round 2
// baseline (speedup 1.0000x reference)
#include <cuda_runtime.h>
#include <cstdint>
#include <cstddef>

// Problem constants (fixed by setup_inputs)
#define BB 2
#define NN 2048
#define DD 1024
#define HH 16
#define DH 64
#define RR (BB*NN)   // 4096 total rows
#define MM 2048      // kv length (start_pos = 0)
#define BUD 1024
#define BIGV (1<<30)

// ---------------- scratch (device globals; no allocation allowed) ----------------
__device__ float g_Yq[(size_t)RR*DD];
__device__ float g_Yk[(size_t)RR*DD];
__device__ float g_Q[(size_t)BB*HH*NN*DH];
__device__ float g_K[(size_t)BB*HH*NN*DH];
__device__ float g_V[(size_t)BB*HH*NN*DH];
__device__ float g_S0[(size_t)BB*NN*MM];
__device__ float g_Fi[BB*MM];
__device__ int   g_ev[BB*MM];
__device__ float g_AO[(size_t)RR*DD];

// ---------------- SGEMM: C(RRxDD) = A(RRxDD) @ B(DDxDD), fp32 ----------------
// 64x64 block tile, BK=16, 256 threads, 4x4 micro-tile.
// scatterV=1 writes C into (B,H,N,Dh) head-major layout instead of row-major.
__global__ void __launch_bounds__(256) sgemm_kernel(
    const float* __restrict__ A, const float* __restrict__ B,
    float* __restrict__ C, int scatterV)
{
    __shared__ float As[64][17];
    __shared__ float Bs[16][64];
    int tid = threadIdx.x;
    int tx = tid & 15, ty = tid >> 4;
    int row0 = blockIdx.y * 64, col0 = blockIdx.x * 64;
    float acc[4][4] = {};
    int ar = tid >> 2, ac = (tid & 3) << 2;
    int br = tid >> 4, bc = (tid & 15) << 2;

    for (int k0 = 0; k0 < DD; k0 += 16) {
        float4 av = *(const float4*)(A + (size_t)(row0 + ar)*DD + k0 + ac);
        As[ar][ac+0] = av.x; As[ar][ac+1] = av.y; As[ar][ac+2] = av.z; As[ar][ac+3] = av.w;
        float4 bv = *(const float4*)(B + (size_t)(k0 + br)*DD + col0 + bc);
        *(float4*)&Bs[br][bc] = bv;
        __syncthreads();
#pragma unroll
        for (int k = 0; k < 16; ++k) {
            float a0 = As[ty*4+0][k], a1 = As[ty*4+1][k];
            float a2 = As[ty*4+2][k], a3 = As[ty*4+3][k];
            float4 b4 = *(const float4*)&Bs[k][tx*4];
            acc[0][0] += a0*b4.x; acc[0][1] += a0*b4.y; acc[0][2] += a0*b4.z; acc[0][3] += a0*b4.w;
            acc[1][0] += a1*b4.x; acc[1][1] += a1*b4.y; acc[1][2] += a1*b4.z; acc[1][3] += a1*b4.w;
            acc[2][0] += a2*b4.x; acc[2][1] += a2*b4.y; acc[2][2] += a2*b4.z; acc[2][3] += a2*b4.w;
            acc[3][0] += a3*b4.x; acc[3][1] += a3*b4.y; acc[3][2] += a3*b4.z; acc[3][3] += a3*b4.w;
        }
        __syncthreads();
    }
    if (!scatterV) {
#pragma unroll
        for (int i = 0; i < 4; ++i) {
            int r = row0 + ty*4 + i;
            float4 w = make_float4(acc[i][0], acc[i][1], acc[i][2], acc[i][3]);
            *(float4*)(C + (size_t)r*DD + col0 + tx*4) = w;
        }
    } else {
#pragma unroll
        for (int i = 0; i < 4; ++i) {
            int r = row0 + ty*4 + i;
            int c = col0 + tx*4;
            int b = r >> 11, n = r & (NN-1);
            int h = c >> 6,  dh = c & (DH-1);
            float4 w = make_float4(acc[i][0], acc[i][1], acc[i][2], acc[i][3]);
            *(float4*)(C + (((size_t)b*HH + h)*NN + n)*DH + dh) = w;
        }
    }
}

// ---------------- LayerNorm over D=1024 per row, scatter to (B,H,N,Dh) ----------------
__global__ void __launch_bounds__(256) ln_scatter_kernel(
    const float* __restrict__ Y, const float* __restrict__ gam,
    const float* __restrict__ bet, float* __restrict__ O)
{
    int row = blockIdx.x, t = threadIdx.x;
    const float* y = Y + (size_t)row * DD;
    float x0 = y[t], x1 = y[t+256], x2 = y[t+512], x3 = y[t+768];
    float s = x0+x1+x2+x3;
    float q = x0*x0 + x1*x1 + x2*x2 + x3*x3;
#pragma unroll
    for (int off = 16; off; off >>= 1) {
        s += __shfl_xor_sync(0xffffffffu, s, off);
        q += __shfl_xor_sync(0xffffffffu, q, off);
    }
    __shared__ float ss[8], sq[8];
    __shared__ float smu, srstd;
    if ((t & 31) == 0) { ss[t>>5] = s; sq[t>>5] = q; }
    __syncthreads();
    if (t == 0) {
        float S = 0.f, Q = 0.f;
#pragma unroll
        for (int i = 0; i < 8; ++i) { S += ss[i]; Q += sq[i]; }
        float mu = S * (1.0f/DD);
        float var = Q * (1.0f/DD) - mu*mu;
        smu = mu; srstd = rsqrtf(var + 1e-5f);
    }
    __syncthreads();
    float mu = smu, rs = srstd;
    int b = row >> 11, n = row & (NN-1);
    float xs[4] = {x0, x1, x2, x3};
#pragma unroll
    for (int i = 0; i < 4; ++i) {
        int d = t + i*256;
        float v = (xs[i] - mu) * rs * gam[d] + bet[d];
        O[(((size_t)b*HH + (d>>6))*NN + n)*DH + (d & (DH-1))] = v;
    }
}

// ---------------- S0[b,j,m] = relu(q0[j]·k0[m]/8), 0 if m==0 or m>=j ----------------
__global__ void __launch_bounds__(256) s0_kernel(
    const float* __restrict__ Qv, const float* __restrict__ Kv, float* __restrict__ S0)
{
    int b  = blockIdx.z;
    int j0 = blockIdx.y << 6, m0 = blockIdx.x << 6;
    int tid = threadIdx.x;
    size_t outbase = ((size_t)b*NN + j0)*MM + m0;
    if (m0 >= j0 + 64) {  // strictly upper-triangular tile: all-zero
        for (int idx = tid; idx < 4096; idx += 256) {
            int jj = idx >> 6, mm = idx & 63;
            S0[outbase + (size_t)jj*MM + mm] = 0.f;
        }
        return;
    }
    __shared__ float Qs[64][68];
    __shared__ float Kts[64][64];
    const float* Qb = Qv + (((size_t)b*HH + 0)*NN + j0)*DH;   // head 0
    const float* Kb = Kv + (((size_t)b*HH + 0)*NN + m0)*DH;
    int r = tid >> 2, c0 = (tid & 3) << 4;
#pragma unroll
    for (int u = 0; u < 4; ++u) {
        float4 v = *(const float4*)(Qb + (size_t)r*DH + c0 + u*4);
        Qs[r][c0+u*4+0] = v.x; Qs[r][c0+u*4+1] = v.y; Qs[r][c0+u*4+2] = v.z; Qs[r][c0+u*4+3] = v.w;
        float4 w = *(const float4*)(Kb + (size_t)r*DH + c0 + u*4);
        Kts[c0+u*4+0][r] = w.x; Kts[c0+u*4+1][r] = w.y; Kts[c0+u*4+2][r] = w.z; Kts[c0+u*4+3][r] = w.w;
    }
    __syncthreads();
    int tx = tid & 15, ty = tid >> 4;
    float acc[4][4] = {};
#pragma unroll 8
    for (int k = 0; k < 64; ++k) {
        float a0 = Qs[ty*4+0][k], a1 = Qs[ty*4+1][k];
        float a2 = Qs[ty*4+2][k], a3 = Qs[ty*4+3][k];
        float4 b4 = *(const float4*)&Kts[k][tx*4];
        acc[0][0] += a0*b4.x; acc[0][1] += a0*b4.y; acc[0][2] += a0*b4.z; acc[0][3] += a0*b4.w;
        acc[1][0] += a1*b4.x; acc[1][1] += a1*b4.y; acc[1][2] += a1*b4.z; acc[1][3] += a1*b4.w;
        acc[2][0] += a2*b4.x; acc[2][1] += a2*b4.y; acc[2][2] += a2*b4.z; acc[2][3] += a2*b4.w;
        acc[3][0] += a3*b4.x; acc[3][1] += a3*b4.y; acc[3][2] += a3*b4.z; acc[3][3] += a3*b4.w;
    }
#pragma unroll
    for (int i = 0; i < 4; ++i) {
        int j = j0 + ty*4 + i;
        int mb = m0 + tx*4;
        float4 w;
        w.x = ((mb+0) == 0 || (mb+0) >= j) ? 0.f : fmaxf(acc[i][0]*0.125f, 0.f);
        w.y = ((mb+1) == 0 || (mb+1) >= j) ? 0.f : fmaxf(acc[i][1]*0.125f, 0.f);
        w.z = ((mb+2) == 0 || (mb+2) >= j) ? 0.f : fmaxf(acc[i][2]*0.125f, 0.f);
        w.w = ((mb+3) == 0 || (mb+3) >= j) ? 0.f : fmaxf(acc[i][3]*0.125f, 0.f);
        *(float4*)(S0 + ((size_t)b*NN + j)*MM + mb) = w;
    }
}

// ---------------- Finit[b,m] = sum_{j<1024} S0[b,j,m]  (deterministic) ----------------
__global__ void __launch_bounds__(256) finit_kernel(
    const float* __restrict__ S0, float* __restrict__ Fi)
{
    int b = blockIdx.y;
    int col = (blockIdx.x << 6) + (threadIdx.x & 63);
    int part = threadIdx.x >> 6;             // 4 parts of 256 rows
    const float* base = S0 + ((size_t)b*NN + part*256)*MM + col;
    float s = 0.f;
#pragma unroll 4
    for (int r = 0; r < 256; ++r) s += base[(size_t)r*MM];
    __shared__ float ps[256];
    ps[threadIdx.x] = s;
    __syncthreads();
    if (threadIdx.x < 64) {
        Fi[b*MM + (blockIdx.x << 6) + threadIdx.x] =
            ps[threadIdx.x] + ps[threadIdx.x+64] + ps[threadIdx.x+128] + ps[threadIdx.x+192];
    }
}

// ---------------- serial heavy-hitter eviction scan (1 block per batch) ----------------
// Fact used: the newly inserted candidate i always has Fm score exactly 0 and ties break
// to earlier positions, so it is never evicted -> argmax over the 1024 resident keys only.
__global__ void __launch_bounds__(1024) scan_kernel(
    const float* __restrict__ S0, const float* __restrict__ Fi, int* __restrict__ evict)
{
    __shared__ float F[2048];
    __shared__ int unm[1024];
    __shared__ float wv[32];
    __shared__ int wp[32];
    __shared__ int s_idx;
    int b = blockIdx.x, t = threadIdx.x;
    F[t]        = Fi[b*MM + t];
    F[t + 1024] = Fi[b*MM + 1024 + t];
    unm[t] = t;
    evict[b*MM + t] = BIGV;
    evict[b*MM + 1024 + t] = BIGV;
    const float* Sb = S0 + (size_t)b*NN*MM;
    float r0 = 0.f, r1 = 0.f;          // row to add at this step (row i-1; none for i=1024)
    __syncthreads();
    for (int i = 1024; i < 2048; ++i) {
        F[t]        += r0;
        F[t + 1024] += r1;
        // prefetch row i (added at step i+1) while the reduction runs
        const float* nrow = Sb + (size_t)i*MM;
        r0 = nrow[t]; r1 = nrow[t + 1024];
        __syncthreads();
        // argmax over resident candidates, tie -> smallest position
        float v = F[unm[t]];
        int   p = t;
#pragma unroll
        for (int off = 16; off; off >>= 1) {
            float ov = __shfl_down_sync(0xffffffffu, v, off);
            int   op = __shfl_down_sync(0xffffffffu, p, off);
            if (ov > v || (ov == v && op < p)) { v = ov; p = op; }
        }
        if ((t & 31) == 0) { wv[t>>5] = v; wp[t>>5] = p; }
        __syncthreads();
        if (t < 32) {
            v = wv[t]; p = wp[t];
#pragma unroll
            for (int off = 16; off; off >>= 1) {
                float ov = __shfl_down_sync(0xffffffffu, v, off);
                int   op = __shfl_down_sync(0xffffffffu, p, off);
                if (ov > v || (ov == v && op < p)) { v = ov; p = op; }
            }
            if (t == 0) s_idx = p;
        }
        __syncthreads();
        int idx = s_idx;
        if (t == idx) evict[b*MM + unm[idx]] = i;
        int nv = (t < idx) ? unm[t] : (t < 1023 ? unm[t+1] : i);   // shift-left + append i
        __syncthreads();
        unm[t] = nv;
        __syncthreads();
    }
}

// ---------------- flash-style fp32 attention with causal + prune mask ----------------
__global__ void __launch_bounds__(256) attn_kernel(
    const float* __restrict__ Qv, const float* __restrict__ Kv,
    const float* __restrict__ Vv, const int* __restrict__ ev_g,
    float* __restrict__ AO)
{
    extern __shared__ float sm[];
    float* Qs  = sm;                 // 64x68
    float* Ps  = sm + 64*68;         // 64x68
    float* Kts = sm + 2*64*68;       // 64x64 (transposed: [k][m])
    float* Vs  = Kts + 64*64;        // 64x64
    int*   evs = (int*)(Vs + 64*64); // 64

    int bq = (int)gridDim.x - 1 - (int)blockIdx.x;  // heavy (late) tiles scheduled first
    int h = blockIdx.y, b = blockIdx.z;
    int nq0 = bq << 6;
    int tid = threadIdx.x;
    int tx = tid & 15, ty = tid >> 4;

    const float* Qb = Qv + (((size_t)b*HH + h)*NN + nq0)*DH;
    {
        int r = tid >> 2, c0 = (tid & 3) << 4;
#pragma unroll
        for (int u = 0; u < 4; ++u) {
            float4 v = *(const float4*)(Qb + (size_t)r*DH + c0 + u*4);
            Qs[r*68 + c0+u*4+0] = v.x; Qs[r*68 + c0+u*4+1] = v.y;
            Qs[r*68 + c0+u*4+2] = v.z; Qs[r*68 + c0+u*4+3] = v.w;
        }
    }
    float mrow[4], lrow[4], o[4][4];
#pragma unroll
    for (int i = 0; i < 4; ++i) {
        mrow[i] = -1e30f; lrow[i] = 0.f;
#pragma unroll
        for (int j = 0; j < 4; ++j) o[i][j] = 0.f;
    }

    for (int kt = 0; kt <= bq; ++kt) {
        int m0 = kt << 6;
        const float* Kb = Kv + (((size_t)b*HH + h)*NN + m0)*DH;
        const float* Vb = Vv + (((size_t)b*HH + h)*NN + m0)*DH;
        __syncthreads();   // previous tile's Kts/Vs/Ps reads are done
        {
            int r = tid >> 2, c0 = (tid & 3) << 4;
#pragma unroll
            for (int u = 0; u < 4; ++u) {
                float4 v = *(const float4*)(Kb + (size_t)r*DH + c0 + u*4);
                Kts[(c0+u*4+0)*64 + r] = v.x; Kts[(c0+u*4+1)*64 + r] = v.y;
                Kts[(c0+u*4+2)*64 + r] = v.z; Kts[(c0+u*4+3)*64 + r] = v.w;
                float4 w = *(const float4*)(Vb + (size_t)r*DH + c0 + u*4);
                *(float4*)&Vs[r*64 + c0 + u*4] = w;
            }
        }
        if (tid < 64) evs[tid] = ev_g[b*MM + m0 + tid];
        __syncthreads();

        // S = Q K^T
        float acc[4][4] = {};
#pragma unroll 8
        for (int k = 0; k < 64; ++k) {
            float a0 = Qs[(ty*4+0)*68 + k], a1 = Qs[(ty*4+1)*68 + k];
            float a2 = Qs[(ty*4+2)*68 + k], a3 = Qs[(ty*4+3)*68 + k];
            float4 b4 = *(const float4*)&Kts[k*64 + tx*4];
            acc[0][0] += a0*b4.x; acc[0][1] += a0*b4.y; acc[0][2] += a0*b4.z; acc[0][3] += a0*b4.w;
            acc[1][0] += a1*b4.x; acc[1][1] += a1*b4.y; acc[1][2] += a1*b4.z; acc[1][3] += a1*b4.w;
            acc[2][0] += a2*b4.x; acc[2][1] += a2*b4.y; acc[2][2] += a2*b4.z; acc[2][3] += a2*b4.w;
            acc[3][0] += a3*b4.x; acc[3][1] += a3*b4.y; acc[3][2] += a3*b4.z; acc[3][3] += a3*b4.w;
        }
        // mask: causal (m<=n) AND not-yet-evicted (n < evict_time[m])
        int ev4[4];
#pragma unroll
        for (int j = 0; j < 4; ++j) ev4[j] = evs[tx*4 + j];
#pragma unroll
        for (int i = 0; i < 4; ++i) {
            int n = nq0 + ty*4 + i;
#pragma unroll
            for (int j = 0; j < 4; ++j) {
                int m = m0 + tx*4 + j;
                bool keep = (m <= n) && (n < ev4[j]);
                acc[i][j] = keep ? acc[i][j]*0.125f : -1e30f;
            }
        }
        // online softmax (row stats via tx-shuffles, replicated)
#pragma unroll
        for (int i = 0; i < 4; ++i) {
            float tm = fmaxf(fmaxf(acc[i][0], acc[i][1]), fmaxf(acc[i][2], acc[i][3]));
#pragma unroll
            for (int off = 8; off; off >>= 1) tm = fmaxf(tm, __shfl_xor_sync(0xffffffffu, tm, off));
            float nm = fmaxf(mrow[i], tm);
            float alpha = __expf(mrow[i] - nm);
            float rsum = 0.f;
#pragma unroll
            for (int j = 0; j < 4; ++j) {
                float pv = (acc[i][j] <= -1e29f) ? 0.f : __expf(acc[i][j] - nm);
                Ps[(ty*4+i)*68 + tx*4 + j] = pv;
                rsum += pv;
            }
#pragma unroll
            for (int off = 8; off; off >>= 1) rsum += __shfl_xor_sync(0xffffffffu, rsum, off);
            lrow[i] = lrow[i]*alpha + rsum;
            mrow[i] = nm;
#pragma unroll
            for (int j = 0; j < 4; ++j) o[i][j] *= alpha;
        }
        __syncthreads();
        // O += P @ V
#pragma unroll 8
        for (int k = 0; k < 64; ++k) {
            float p0 = Ps[(ty*4+0)*68 + k], p1 = Ps[(ty*4+1)*68 + k];
            float p2 = Ps[(ty*4+2)*68 + k], p3 = Ps[(ty*4+3)*68 + k];
            float4 v = *(const float4*)&Vs[k*64 + tx*4];
            o[0][0] += p0*v.x; o[0][1] += p0*v.y; o[0][2] += p0*v.z; o[0][3] += p0*v.w;
            o[1][0] += p1*v.x; o[1][1] += p1*v.y; o[1][2] += p1*v.z; o[1][3] += p1*v.w;
            o[2][0] += p2*v.x; o[2][1] += p2*v.y; o[2][2] += p2*v.z; o[2][3] += p2*v.w;
            o[3][0] += p3*v.x; o[3][1] += p3*v.y; o[3][2] += p3*v.z; o[3][3] += p3*v.w;
        }
    }
#pragma unroll
    for (int i = 0; i < 4; ++i) {
        float rl = 1.0f / lrow[i];
        int n = nq0 + ty*4 + i;
        float4 w = make_float4(o[i][0]*rl, o[i][1]*rl, o[i][2]*rl, o[i][3]*rl);
        *(float4*)(AO + ((size_t)b*NN + n)*DD + h*DH + tx*4) = w;
    }
}

#define ATT_SMEM ((64*68*2 + 64*64*2)*4 + 64*4)

extern "C" void kernel_launch(void* const* d_in, const int* in_sizes, int n_in,
                              void* d_out, int out_size)
{
    (void)in_sizes; (void)n_in; (void)out_size;
    const float* X  = (const float*)d_in[0];
    const float* Wq = (const float*)d_in[1];
    const float* Wk = (const float*)d_in[2];
    const float* Wv = (const float*)d_in[3];
    const float* Wo = (const float*)d_in[4];
    const float* gq = (const float*)d_in[5];
    const float* bq = (const float*)d_in[6];
    const float* gk = (const float*)d_in[7];
    const float* bk = (const float*)d_in[8];
    // d_in[9..11]: cache_k, cache_v, start_pos — unused (start_pos = 0)
    float* out = (float*)d_out;

    float *Yq, *Yk, *Qp, *Kp, *Vp, *S0, *Fi, *AO; int* ev;
    cudaGetSymbolAddress((void**)&Yq, g_Yq);
    cudaGetSymbolAddress((void**)&Yk, g_Yk);
    cudaGetSymbolAddress((void**)&Qp, g_Q);
    cudaGetSymbolAddress((void**)&Kp, g_K);
    cudaGetSymbolAddress((void**)&Vp, g_V);
    cudaGetSymbolAddress((void**)&S0, g_S0);
    cudaGetSymbolAddress((void**)&Fi, g_Fi);
    cudaGetSymbolAddress((void**)&ev, g_ev);
    cudaGetSymbolAddress((void**)&AO, g_AO);

    cudaFuncSetAttribute(attn_kernel, cudaFuncAttributeMaxDynamicSharedMemorySize, ATT_SMEM);

    dim3 gg(DD/64, RR/64);
    sgemm_kernel<<<gg, 256>>>(X, Wq, Yq, 0);
    sgemm_kernel<<<gg, 256>>>(X, Wk, Yk, 0);
    sgemm_kernel<<<gg, 256>>>(X, Wv, Vp, 1);
    ln_scatter_kernel<<<RR, 256>>>(Yq, gq, bq, Qp);
    ln_scatter_kernel<<<RR, 256>>>(Yk, gk, bk, Kp);
    s0_kernel<<<dim3(MM/64, NN/64, BB), 256>>>(Qp, Kp, S0);
    finit_kernel<<<dim3(MM/64, BB), 256>>>(S0, Fi);
    scan_kernel<<<BB, 1024>>>(S0, Fi, ev);
    attn_kernel<<<dim3(NN/64, HH, BB), 256, ATT_SMEM>>>(Qp, Kp, Vp, ev, AO);
    sgemm_kernel<<<gg, 256>>>(AO, Wo, out, 0);
}

// round 4
// speedup vs baseline: 1.0079x; 1.0079x over previous
#include <cuda_runtime.h>
#include <cuda_bf16.h>
#include <mma.h>
#include <cstdint>
#include <cstddef>

using namespace nvcuda;

#define BB 2
#define NN 2048
#define DD 1024
#define HH 16
#define DH 64
#define RR (BB*NN)
#define MM 2048
#define BIGV (1<<30)

// ---------------- scratch ----------------
__device__ float g_Yq[(size_t)RR*DD];
__device__ float g_Yk[(size_t)RR*DD];
__device__ float g_Q[(size_t)BB*HH*NN*DH];
__device__ float g_K[(size_t)BB*HH*NN*DH];
__device__ float g_V[(size_t)BB*HH*NN*DH];
__device__ float g_S0[(size_t)BB*NN*MM];
__device__ float g_Fi[BB*MM];
__device__ int   g_ev[BB*MM];
__device__ float g_AO[(size_t)RR*DD];
__device__ __nv_bfloat16 g_Xh[(size_t)RR*DD], g_Xm[(size_t)RR*DD], g_Xl[(size_t)RR*DD];
__device__ __nv_bfloat16 g_Wqh[(size_t)DD*DD], g_Wqm[(size_t)DD*DD], g_Wql[(size_t)DD*DD];
__device__ __nv_bfloat16 g_Wkh[(size_t)DD*DD], g_Wkm[(size_t)DD*DD], g_Wkl[(size_t)DD*DD];
__device__ __nv_bfloat16 g_Wvh[(size_t)DD*DD], g_Wvm[(size_t)DD*DD];
__device__ __nv_bfloat16 g_Woh[(size_t)DD*DD], g_Wom[(size_t)DD*DD];
__device__ __nv_bfloat16 g_Ah[(size_t)RR*DD], g_Am[(size_t)RR*DD];

// ---------------- conversions ----------------
__global__ void __launch_bounds__(256) conv3_kernel(
    const float* __restrict__ X, __nv_bfloat16* __restrict__ H,
    __nv_bfloat16* __restrict__ Mp, __nv_bfloat16* __restrict__ L)
{
    int i = blockIdx.x * 256 + threadIdx.x;
    float v = X[i];
    __nv_bfloat16 h = __float2bfloat16(v);
    float r1 = v - __bfloat162float(h);
    __nv_bfloat16 m = __float2bfloat16(r1);
    H[i] = h; Mp[i] = m;
    if (L) L[i] = __float2bfloat16(r1 - __bfloat162float(m));
}

// transpose + split: T*[n][k] = split(W[k][n]); TL optional
__global__ void __launch_bounds__(256) convW_kernel(
    const float* __restrict__ W, __nv_bfloat16* __restrict__ TH,
    __nv_bfloat16* __restrict__ TM, __nv_bfloat16* __restrict__ TL)
{
    __shared__ float tile[32][33];
    int n0 = blockIdx.x * 32, k0 = blockIdx.y * 32;
    int tx = threadIdx.x, ty = threadIdx.y;   // 32 x 8
#pragma unroll
    for (int i = 0; i < 32; i += 8)
        tile[ty + i][tx] = W[(size_t)(k0 + ty + i) * DD + n0 + tx];
    __syncthreads();
#pragma unroll
    for (int i = 0; i < 32; i += 8) {
        float v = tile[tx][ty + i];
        __nv_bfloat16 h = __float2bfloat16(v);
        float r1 = v - __bfloat162float(h);
        __nv_bfloat16 m = __float2bfloat16(r1);
        size_t o = (size_t)(n0 + ty + i) * DD + k0 + tx;
        TH[o] = h; TM[o] = m;
        if (TL) TL[o] = __float2bfloat16(r1 - __bfloat162float(m));
    }
}

// ---------------- WMMA split-bf16 GEMM ----------------
// C[4096x1024] = A @ W ; A parts row-major (m,k), W parts pre-transposed (n,k).
// Accumulates all split products (i,j) with i+j<NS into fp32 accumulators.
// Block 128x64, 8 warps (4m x 2n), warp tile 32x32, BK=32.
#define PARTA (128*48)
#define PARTB (64*48)
#define GW_SMEM(NS) ((NS)*(PARTA+PARTB)*2)

template<int NS>
__global__ void __launch_bounds__(256) gemm_wmma_kernel(
    const __nv_bfloat16* __restrict__ A0, const __nv_bfloat16* __restrict__ A1,
    const __nv_bfloat16* __restrict__ A2,
    const __nv_bfloat16* __restrict__ B0, const __nv_bfloat16* __restrict__ B1,
    const __nv_bfloat16* __restrict__ B2,
    float* __restrict__ C, int scatter)
{
    extern __shared__ __nv_bfloat16 smw[];
    __nv_bfloat16* As = smw;                 // NS parts, each 128 x 48 (BK=32 + pad)
    __nv_bfloat16* Bs = smw + NS*PARTA;      // NS parts, each 64 x 48
    int tid = threadIdx.x;
    int wid = tid >> 5;
    int wm = wid & 3, wn = wid >> 2;         // 4 x 2 warp grid
    int row0 = blockIdx.y * 128, col0 = blockIdx.x * 64;

    const __nv_bfloat16* aps[3];
    const __nv_bfloat16* bps[3];
    aps[0] = A0; aps[1] = A1; aps[2] = (NS > 2) ? A2 : A0;
    bps[0] = B0; bps[1] = B1; bps[2] = (NS > 2) ? B2 : B0;

    wmma::fragment<wmma::accumulator, 16, 16, 16, float> acc[2][2];
#pragma unroll
    for (int i = 0; i < 2; ++i)
#pragma unroll
        for (int j = 0; j < 2; ++j) wmma::fill_fragment(acc[i][j], 0.0f);

    // per-thread load coords
    int ar0 = (tid * 2) >> 2,  ac0 = ((tid * 2) & 3) * 8;     // A: 2 uint4/thread/part
    int ar1 = (tid * 2 + 1) >> 2, ac1 = ((tid * 2 + 1) & 3) * 8;
    int br = tid >> 2, bc = (tid & 3) * 8;                    // B: 1 uint4/thread/part

    for (int kb = 0; kb < DD; kb += 32) {
        __syncthreads();
#pragma unroll
        for (int p = 0; p < NS; ++p) {
            *(uint4*)(As + p*PARTA + ar0*48 + ac0) =
                *(const uint4*)(aps[p] + (size_t)(row0 + ar0)*DD + kb + ac0);
            *(uint4*)(As + p*PARTA + ar1*48 + ac1) =
                *(const uint4*)(aps[p] + (size_t)(row0 + ar1)*DD + kb + ac1);
            *(uint4*)(Bs + p*PARTB + br*48 + bc) =
                *(const uint4*)(bps[p] + (size_t)(col0 + br)*DD + kb + bc);
        }
        __syncthreads();
#pragma unroll
        for (int ks = 0; ks < 32; ks += 16) {
#pragma unroll
            for (int pi = 0; pi < NS; ++pi) {
#pragma unroll
                for (int pj = 0; pj < NS; ++pj) {
                    if (pi + pj >= NS) continue;
                    wmma::fragment<wmma::matrix_a, 16, 16, 16, __nv_bfloat16, wmma::row_major> af[2];
                    wmma::fragment<wmma::matrix_b, 16, 16, 16, __nv_bfloat16, wmma::col_major> bf[2];
                    wmma::load_matrix_sync(af[0], As + pi*PARTA + (wm*32 +  0)*48 + ks, 48);
                    wmma::load_matrix_sync(af[1], As + pi*PARTA + (wm*32 + 16)*48 + ks, 48);
                    wmma::load_matrix_sync(bf[0], Bs + pj*PARTB + (wn*32 +  0)*48 + ks, 48);
                    wmma::load_matrix_sync(bf[1], Bs + pj*PARTB + (wn*32 + 16)*48 + ks, 48);
#pragma unroll
                    for (int mi = 0; mi < 2; ++mi)
#pragma unroll
                        for (int ni = 0; ni < 2; ++ni)
                            wmma::mma_sync(acc[mi][ni], af[mi], bf[ni], acc[mi][ni]);
                }
            }
        }
    }

#pragma unroll
    for (int mi = 0; mi < 2; ++mi)
#pragma unroll
        for (int ni = 0; ni < 2; ++ni) {
            int r = row0 + wm*32 + mi*16;
            int c = col0 + wn*32 + ni*16;
            if (!scatter) {
                wmma::store_matrix_sync(C + (size_t)r*DD + c, acc[mi][ni], DD, wmma::mem_row_major);
            } else {
                int b = r >> 11, nrow = r & (NN - 1);
                int h = c >> 6,  dh = c & (DH - 1);
                wmma::store_matrix_sync(C + (((size_t)b*HH + h)*NN + nrow)*DH + dh,
                                        acc[mi][ni], DH, wmma::mem_row_major);
            }
        }
}

// ---------------- LayerNorm + head scatter ----------------
__global__ void __launch_bounds__(256) ln_scatter_kernel(
    const float* __restrict__ Y, const float* __restrict__ gam,
    const float* __restrict__ bet, float* __restrict__ O)
{
    int row = blockIdx.x, t = threadIdx.x;
    const float* y = Y + (size_t)row * DD;
    float x0 = y[t], x1 = y[t+256], x2 = y[t+512], x3 = y[t+768];
    float s = x0+x1+x2+x3;
    float q = x0*x0 + x1*x1 + x2*x2 + x3*x3;
#pragma unroll
    for (int off = 16; off; off >>= 1) {
        s += __shfl_xor_sync(0xffffffffu, s, off);
        q += __shfl_xor_sync(0xffffffffu, q, off);
    }
    __shared__ float ss[8], sq[8];
    __shared__ float smu, srstd;
    if ((t & 31) == 0) { ss[t>>5] = s; sq[t>>5] = q; }
    __syncthreads();
    if (t == 0) {
        float S = 0.f, Q = 0.f;
#pragma unroll
        for (int i = 0; i < 8; ++i) { S += ss[i]; Q += sq[i]; }
        float mu = S * (1.0f/DD);
        float var = Q * (1.0f/DD) - mu*mu;
        smu = mu; srstd = rsqrtf(var + 1e-5f);
    }
    __syncthreads();
    float mu = smu, rs = srstd;
    int b = row >> 11, n = row & (NN-1);
    float xs[4] = {x0, x1, x2, x3};
#pragma unroll
    for (int i = 0; i < 4; ++i) {
        int d = t + i*256;
        float v = (xs[i] - mu) * rs * gam[d] + bet[d];
        O[(((size_t)b*HH + (d>>6))*NN + n)*DH + (d & (DH-1))] = v;
    }
}

// ---------------- S0 ----------------
__global__ void __launch_bounds__(256) s0_kernel(
    const float* __restrict__ Qv, const float* __restrict__ Kv, float* __restrict__ S0)
{
    int b  = blockIdx.z;
    int j0 = blockIdx.y << 6, m0 = blockIdx.x << 6;
    int tid = threadIdx.x;
    size_t outbase = ((size_t)b*NN + j0)*MM + m0;
    if (m0 >= j0 + 64) {
        for (int idx = tid; idx < 4096; idx += 256) {
            int jj = idx >> 6, mm = idx & 63;
            S0[outbase + (size_t)jj*MM + mm] = 0.f;
        }
        return;
    }
    __shared__ float Qs[64][68];
    __shared__ float Kts[64][64];
    const float* Qb = Qv + (((size_t)b*HH + 0)*NN + j0)*DH;
    const float* Kb = Kv + (((size_t)b*HH + 0)*NN + m0)*DH;
    int r = tid >> 2, c0 = (tid & 3) << 4;
#pragma unroll
    for (int u = 0; u < 4; ++u) {
        float4 v = *(const float4*)(Qb + (size_t)r*DH + c0 + u*4);
        Qs[r][c0+u*4+0] = v.x; Qs[r][c0+u*4+1] = v.y; Qs[r][c0+u*4+2] = v.z; Qs[r][c0+u*4+3] = v.w;
        float4 w = *(const float4*)(Kb + (size_t)r*DH + c0 + u*4);
        Kts[c0+u*4+0][r] = w.x; Kts[c0+u*4+1][r] = w.y; Kts[c0+u*4+2][r] = w.z; Kts[c0+u*4+3][r] = w.w;
    }
    __syncthreads();
    int tx = tid & 15, ty = tid >> 4;
    float acc[4][4] = {};
#pragma unroll 8
    for (int k = 0; k < 64; ++k) {
        float a0 = Qs[ty*4+0][k], a1 = Qs[ty*4+1][k];
        float a2 = Qs[ty*4+2][k], a3 = Qs[ty*4+3][k];
        float4 b4 = *(const float4*)&Kts[k][tx*4];
        acc[0][0] += a0*b4.x; acc[0][1] += a0*b4.y; acc[0][2] += a0*b4.z; acc[0][3] += a0*b4.w;
        acc[1][0] += a1*b4.x; acc[1][1] += a1*b4.y; acc[1][2] += a1*b4.z; acc[1][3] += a1*b4.w;
        acc[2][0] += a2*b4.x; acc[2][1] += a2*b4.y; acc[2][2] += a2*b4.z; acc[2][3] += a2*b4.w;
        acc[3][0] += a3*b4.x; acc[3][1] += a3*b4.y; acc[3][2] += a3*b4.z; acc[3][3] += a3*b4.w;
    }
#pragma unroll
    for (int i = 0; i < 4; ++i) {
        int j = j0 + ty*4 + i;
        int mb = m0 + tx*4;
        float4 w;
        w.x = ((mb+0) == 0 || (mb+0) >= j) ? 0.f : fmaxf(acc[i][0]*0.125f, 0.f);
        w.y = ((mb+1) == 0 || (mb+1) >= j) ? 0.f : fmaxf(acc[i][1]*0.125f, 0.f);
        w.z = ((mb+2) == 0 || (mb+2) >= j) ? 0.f : fmaxf(acc[i][2]*0.125f, 0.f);
        w.w = ((mb+3) == 0 || (mb+3) >= j) ? 0.f : fmaxf(acc[i][3]*0.125f, 0.f);
        *(float4*)(S0 + ((size_t)b*NN + j)*MM + mb) = w;
    }
}

// ---------------- Finit ----------------
__global__ void __launch_bounds__(256) finit_kernel(
    const float* __restrict__ S0, float* __restrict__ Fi)
{
    int b = blockIdx.y;
    int col = (blockIdx.x << 6) + (threadIdx.x & 63);
    int part = threadIdx.x >> 6;
    const float* base = S0 + ((size_t)b*NN + part*256)*MM + col;
    float s = 0.f;
#pragma unroll 4
    for (int r = 0; r < 256; ++r) s += base[(size_t)r*MM];
    __shared__ float ps[256];
    ps[threadIdx.x] = s;
    __syncthreads();
    if (threadIdx.x < 64) {
        Fi[b*MM + (blockIdx.x << 6) + threadIdx.x] =
            ps[threadIdx.x] + ps[threadIdx.x+64] + ps[threadIdx.x+128] + ps[threadIdx.x+192];
    }
}

// ---------------- serial eviction scan ----------------
__global__ void __launch_bounds__(1024) scan_kernel(
    const float* __restrict__ S0, const float* __restrict__ Fi, int* __restrict__ evict)
{
    __shared__ float F[2048];
    __shared__ int unm[1024];
    __shared__ float wv[32];
    __shared__ int wp[32];
    __shared__ int s_idx;
    int b = blockIdx.x, t = threadIdx.x;
    F[t]        = Fi[b*MM + t];
    F[t + 1024] = Fi[b*MM + 1024 + t];
    unm[t] = t;
    evict[b*MM + t] = BIGV;
    evict[b*MM + 1024 + t] = BIGV;
    const float* Sb = S0 + (size_t)b*NN*MM;
    float r0 = 0.f, r1 = 0.f;
    __syncthreads();
    for (int i = 1024; i < 2048; ++i) {
        F[t]        += r0;
        F[t + 1024] += r1;
        const float* nrow = Sb + (size_t)i*MM;
        r0 = nrow[t]; r1 = nrow[t + 1024];
        __syncthreads();
        float v = F[unm[t]];
        int   p = t;
#pragma unroll
        for (int off = 16; off; off >>= 1) {
            float ov = __shfl_down_sync(0xffffffffu, v, off);
            int   op = __shfl_down_sync(0xffffffffu, p, off);
            if (ov > v || (ov == v && op < p)) { v = ov; p = op; }
        }
        if ((t & 31) == 0) { wv[t>>5] = v; wp[t>>5] = p; }
        __syncthreads();
        if (t < 32) {
            v = wv[t]; p = wp[t];
#pragma unroll
            for (int off = 16; off; off >>= 1) {
                float ov = __shfl_down_sync(0xffffffffu, v, off);
                int   op = __shfl_down_sync(0xffffffffu, p, off);
                if (ov > v || (ov == v && op < p)) { v = ov; p = op; }
            }
            if (t == 0) s_idx = p;
        }
        __syncthreads();
        int idx = s_idx;
        if (t == idx) evict[b*MM + unm[idx]] = i;
        int nv = (t < idx) ? unm[t] : (t < 1023 ? unm[t+1] : i);
        __syncthreads();
        unm[t] = nv;
        __syncthreads();
    }
}

// ---------------- flash attention fp32 ----------------
__global__ void __launch_bounds__(256) attn_kernel(
    const float* __restrict__ Qv, const float* __restrict__ Kv,
    const float* __restrict__ Vv, const int* __restrict__ ev_g,
    float* __restrict__ AO)
{
    extern __shared__ float sm[];
    float* Qs  = sm;
    float* Ps  = sm + 64*68;
    float* Kts = sm + 2*64*68;
    float* Vs  = Kts + 64*64;
    int*   evs = (int*)(Vs + 64*64);

    int bq = (int)gridDim.x - 1 - (int)blockIdx.x;
    int h = blockIdx.y, b = blockIdx.z;
    int nq0 = bq << 6;
    int tid = threadIdx.x;
    int tx = tid & 15, ty = tid >> 4;

    const float* Qb = Qv + (((size_t)b*HH + h)*NN + nq0)*DH;
    {
        int r = tid >> 2, c0 = (tid & 3) << 4;
#pragma unroll
        for (int u = 0; u < 4; ++u) {
            float4 v = *(const float4*)(Qb + (size_t)r*DH + c0 + u*4);
            Qs[r*68 + c0+u*4+0] = v.x; Qs[r*68 + c0+u*4+1] = v.y;
            Qs[r*68 + c0+u*4+2] = v.z; Qs[r*68 + c0+u*4+3] = v.w;
        }
    }
    float mrow[4], lrow[4], o[4][4];
#pragma unroll
    for (int i = 0; i < 4; ++i) {
        mrow[i] = -1e30f; lrow[i] = 0.f;
#pragma unroll
        for (int j = 0; j < 4; ++j) o[i][j] = 0.f;
    }

    for (int kt = 0; kt <= bq; ++kt) {
        int m0 = kt << 6;
        const float* Kb = Kv + (((size_t)b*HH + h)*NN + m0)*DH;
        const float* Vb = Vv + (((size_t)b*HH + h)*NN + m0)*DH;
        __syncthreads();
        {
            int r = tid >> 2, c0 = (tid & 3) << 4;
#pragma unroll
            for (int u = 0; u < 4; ++u) {
                float4 v = *(const float4*)(Kb + (size_t)r*DH + c0 + u*4);
                Kts[(c0+u*4+0)*64 + r] = v.x; Kts[(c0+u*4+1)*64 + r] = v.y;
                Kts[(c0+u*4+2)*64 + r] = v.z; Kts[(c0+u*4+3)*64 + r] = v.w;
                float4 w = *(const float4*)(Vb + (size_t)r*DH + c0 + u*4);
                *(float4*)&Vs[r*64 + c0 + u*4] = w;
            }
        }
        if (tid < 64) evs[tid] = ev_g[b*MM + m0 + tid];
        __syncthreads();

        float acc[4][4] = {};
#pragma unroll 8
        for (int k = 0; k < 64; ++k) {
            float a0 = Qs[(ty*4+0)*68 + k], a1 = Qs[(ty*4+1)*68 + k];
            float a2 = Qs[(ty*4+2)*68 + k], a3 = Qs[(ty*4+3)*68 + k];
            float4 b4 = *(const float4*)&Kts[k*64 + tx*4];
            acc[0][0] += a0*b4.x; acc[0][1] += a0*b4.y; acc[0][2] += a0*b4.z; acc[0][3] += a0*b4.w;
            acc[1][0] += a1*b4.x; acc[1][1] += a1*b4.y; acc[1][2] += a1*b4.z; acc[1][3] += a1*b4.w;
            acc[2][0] += a2*b4.x; acc[2][1] += a2*b4.y; acc[2][2] += a2*b4.z; acc[2][3] += a2*b4.w;
            acc[3][0] += a3*b4.x; acc[3][1] += a3*b4.y; acc[3][2] += a3*b4.z; acc[3][3] += a3*b4.w;
        }
        int ev4[4];
#pragma unroll
        for (int j = 0; j < 4; ++j) ev4[j] = evs[tx*4 + j];
#pragma unroll
        for (int i = 0; i < 4; ++i) {
            int n = nq0 + ty*4 + i;
#pragma unroll
            for (int j = 0; j < 4; ++j) {
                int m = m0 + tx*4 + j;
                bool keep = (m <= n) && (n < ev4[j]);
                acc[i][j] = keep ? acc[i][j]*0.125f : -1e30f;
            }
        }
#pragma unroll
        for (int i = 0; i < 4; ++i) {
            float tm = fmaxf(fmaxf(acc[i][0], acc[i][1]), fmaxf(acc[i][2], acc[i][3]));
#pragma unroll
            for (int off = 8; off; off >>= 1) tm = fmaxf(tm, __shfl_xor_sync(0xffffffffu, tm, off));
            float nm = fmaxf(mrow[i], tm);
            float alpha = __expf(mrow[i] - nm);
            float rsum = 0.f;
#pragma unroll
            for (int j = 0; j < 4; ++j) {
                float pv = (acc[i][j] <= -1e29f) ? 0.f : __expf(acc[i][j] - nm);
                Ps[(ty*4+i)*68 + tx*4 + j] = pv;
                rsum += pv;
            }
#pragma unroll
            for (int off = 8; off; off >>= 1) rsum += __shfl_xor_sync(0xffffffffu, rsum, off);
            lrow[i] = lrow[i]*alpha + rsum;
            mrow[i] = nm;
#pragma unroll
            for (int j = 0; j < 4; ++j) o[i][j] *= alpha;
        }
        __syncthreads();
#pragma unroll 8
        for (int k = 0; k < 64; ++k) {
            float p0 = Ps[(ty*4+0)*68 + k], p1 = Ps[(ty*4+1)*68 + k];
            float p2 = Ps[(ty*4+2)*68 + k], p3 = Ps[(ty*4+3)*68 + k];
            float4 v = *(const float4*)&Vs[k*64 + tx*4];
            o[0][0] += p0*v.x; o[0][1] += p0*v.y; o[0][2] += p0*v.z; o[0][3] += p0*v.w;
            o[1][0] += p1*v.x; o[1][1] += p1*v.y; o[1][2] += p1*v.z; o[1][3] += p1*v.w;
            o[2][0] += p2*v.x; o[2][1] += p2*v.y; o[2][2] += p2*v.z; o[2][3] += p2*v.w;
            o[3][0] += p3*v.x; o[3][1] += p3*v.y; o[3][2] += p3*v.z; o[3][3] += p3*v.w;
        }
    }
#pragma unroll
    for (int i = 0; i < 4; ++i) {
        float rl = 1.0f / lrow[i];
        int n = nq0 + ty*4 + i;
        float4 w = make_float4(o[i][0]*rl, o[i][1]*rl, o[i][2]*rl, o[i][3]*rl);
        *(float4*)(AO + ((size_t)b*NN + n)*DD + h*DH + tx*4) = w;
    }
}

#define ATT_SMEM ((64*68*2 + 64*64*2)*4 + 64*4)

extern "C" void kernel_launch(void* const* d_in, const int* in_sizes, int n_in,
                              void* d_out, int out_size)
{
    (void)in_sizes; (void)n_in; (void)out_size;
    const float* X  = (const float*)d_in[0];
    const float* Wq = (const float*)d_in[1];
    const float* Wk = (const float*)d_in[2];
    const float* Wv = (const float*)d_in[3];
    const float* Wo = (const float*)d_in[4];
    const float* gq = (const float*)d_in[5];
    const float* bq = (const float*)d_in[6];
    const float* gk = (const float*)d_in[7];
    const float* bk = (const float*)d_in[8];
    float* out = (float*)d_out;

    float *Yq, *Yk, *Qp, *Kp, *Vp, *S0, *Fi, *AO; int* ev;
    cudaGetSymbolAddress((void**)&Yq, g_Yq);
    cudaGetSymbolAddress((void**)&Yk, g_Yk);
    cudaGetSymbolAddress((void**)&Qp, g_Q);
    cudaGetSymbolAddress((void**)&Kp, g_K);
    cudaGetSymbolAddress((void**)&Vp, g_V);
    cudaGetSymbolAddress((void**)&S0, g_S0);
    cudaGetSymbolAddress((void**)&Fi, g_Fi);
    cudaGetSymbolAddress((void**)&ev, g_ev);
    cudaGetSymbolAddress((void**)&AO, g_AO);
    __nv_bfloat16 *Xh,*Xm,*Xl,*Wqh,*Wqm,*Wql,*Wkh,*Wkm,*Wkl,*Wvh,*Wvm,*Woh,*Wom,*Ah,*Am;
    cudaGetSymbolAddress((void**)&Xh, g_Xh);  cudaGetSymbolAddress((void**)&Xm, g_Xm);
    cudaGetSymbolAddress((void**)&Xl, g_Xl);
    cudaGetSymbolAddress((void**)&Wqh, g_Wqh); cudaGetSymbolAddress((void**)&Wqm, g_Wqm);
    cudaGetSymbolAddress((void**)&Wql, g_Wql);
    cudaGetSymbolAddress((void**)&Wkh, g_Wkh); cudaGetSymbolAddress((void**)&Wkm, g_Wkm);
    cudaGetSymbolAddress((void**)&Wkl, g_Wkl);
    cudaGetSymbolAddress((void**)&Wvh, g_Wvh); cudaGetSymbolAddress((void**)&Wvm, g_Wvm);
    cudaGetSymbolAddress((void**)&Woh, g_Woh); cudaGetSymbolAddress((void**)&Wom, g_Wom);
    cudaGetSymbolAddress((void**)&Ah, g_Ah);   cudaGetSymbolAddress((void**)&Am, g_Am);

    cudaFuncSetAttribute(attn_kernel, cudaFuncAttributeMaxDynamicSharedMemorySize, ATT_SMEM);
    cudaFuncSetAttribute(gemm_wmma_kernel<3>, cudaFuncAttributeMaxDynamicSharedMemorySize, GW_SMEM(3));
    cudaFuncSetAttribute(gemm_wmma_kernel<2>, cudaFuncAttributeMaxDynamicSharedMemorySize, GW_SMEM(2));

    dim3 wgrid(32, 32);
    dim3 ggrid(DD/64, RR/128);

    conv3_kernel<<<RR*DD/256, 256>>>(X, Xh, Xm, Xl);
    convW_kernel<<<wgrid, dim3(32,8)>>>(Wq, Wqh, Wqm, Wql);
    convW_kernel<<<wgrid, dim3(32,8)>>>(Wk, Wkh, Wkm, Wkl);
    convW_kernel<<<wgrid, dim3(32,8)>>>(Wv, Wvh, Wvm, nullptr);
    convW_kernel<<<wgrid, dim3(32,8)>>>(Wo, Woh, Wom, nullptr);
    gemm_wmma_kernel<3><<<ggrid, 256, GW_SMEM(3)>>>(Xh, Xm, Xl, Wqh, Wqm, Wql, Yq, 0);
    gemm_wmma_kernel<3><<<ggrid, 256, GW_SMEM(3)>>>(Xh, Xm, Xl, Wkh, Wkm, Wkl, Yk, 0);
    gemm_wmma_kernel<2><<<ggrid, 256, GW_SMEM(2)>>>(Xh, Xm, nullptr, Wvh, Wvm, nullptr, Vp, 1);
    ln_scatter_kernel<<<RR, 256>>>(Yq, gq, bq, Qp);
    ln_scatter_kernel<<<RR, 256>>>(Yk, gk, bk, Kp);
    s0_kernel<<<dim3(MM/64, NN/64, BB), 256>>>(Qp, Kp, S0);
    finit_kernel<<<dim3(MM/64, BB), 256>>>(S0, Fi);
    scan_kernel<<<BB, 1024>>>(S0, Fi, ev);
    attn_kernel<<<dim3(NN/64, HH, BB), 256, ATT_SMEM>>>(Qp, Kp, Vp, ev, AO);
    conv3_kernel<<<RR*DD/256, 256>>>(AO, Ah, Am, nullptr);
    gemm_wmma_kernel<2><<<ggrid, 256, GW_SMEM(2)>>>(Ah, Am, nullptr, Woh, Wom, nullptr, out, 0);
}

// round 5
// speedup vs baseline: 1.1380x; 1.1291x over previous
#include <cuda_runtime.h>
#include <cuda_bf16.h>
#include <mma.h>
#include <cstdint>
#include <cstddef>

using namespace nvcuda;

#define BB 2
#define NN 2048
#define DD 1024
#define HH 16
#define DH 64
#define RR (BB*NN)
#define MM 2048
#define BIGV (1<<30)

// ---------------- scratch ----------------
__device__ float g_Yq[(size_t)RR*DD];
__device__ float g_Yk[(size_t)RR*DD];
__device__ float g_Q[(size_t)BB*HH*NN*DH];
__device__ float g_K[(size_t)BB*HH*NN*DH];
__device__ float g_V[(size_t)BB*HH*NN*DH];
__device__ float g_S0[(size_t)BB*NN*MM];
__device__ float g_Fi[BB*MM];
__device__ int   g_ev[BB*MM];
__device__ float g_AO[(size_t)RR*DD];
__device__ __nv_bfloat16 g_Xh[(size_t)RR*DD], g_Xm[(size_t)RR*DD], g_Xl[(size_t)RR*DD];
__device__ __nv_bfloat16 g_Wqh[(size_t)DD*DD], g_Wqm[(size_t)DD*DD], g_Wql[(size_t)DD*DD];
__device__ __nv_bfloat16 g_Wkh[(size_t)DD*DD], g_Wkm[(size_t)DD*DD], g_Wkl[(size_t)DD*DD];
__device__ __nv_bfloat16 g_Wvh[(size_t)DD*DD], g_Wvm[(size_t)DD*DD];
__device__ __nv_bfloat16 g_Woh[(size_t)DD*DD], g_Wom[(size_t)DD*DD];
__device__ __nv_bfloat16 g_Ah[(size_t)RR*DD], g_Am[(size_t)RR*DD];

// ---------------- conversions ----------------
__global__ void __launch_bounds__(256) conv3_kernel(
    const float* __restrict__ X, __nv_bfloat16* __restrict__ H,
    __nv_bfloat16* __restrict__ Mp, __nv_bfloat16* __restrict__ L)
{
    int i = blockIdx.x * 256 + threadIdx.x;
    float v = X[i];
    __nv_bfloat16 h = __float2bfloat16(v);
    float r1 = v - __bfloat162float(h);
    __nv_bfloat16 m = __float2bfloat16(r1);
    H[i] = h; Mp[i] = m;
    if (L) L[i] = __float2bfloat16(r1 - __bfloat162float(m));
}

__global__ void __launch_bounds__(256) convW_kernel(
    const float* __restrict__ W, __nv_bfloat16* __restrict__ TH,
    __nv_bfloat16* __restrict__ TM, __nv_bfloat16* __restrict__ TL)
{
    __shared__ float tile[32][33];
    int n0 = blockIdx.x * 32, k0 = blockIdx.y * 32;
    int tx = threadIdx.x, ty = threadIdx.y;
#pragma unroll
    for (int i = 0; i < 32; i += 8)
        tile[ty + i][tx] = W[(size_t)(k0 + ty + i) * DD + n0 + tx];
    __syncthreads();
#pragma unroll
    for (int i = 0; i < 32; i += 8) {
        float v = tile[tx][ty + i];
        __nv_bfloat16 h = __float2bfloat16(v);
        float r1 = v - __bfloat162float(h);
        __nv_bfloat16 m = __float2bfloat16(r1);
        size_t o = (size_t)(n0 + ty + i) * DD + k0 + tx;
        TH[o] = h; TM[o] = m;
        if (TL) TL[o] = __float2bfloat16(r1 - __bfloat162float(m));
    }
}

// ---------------- WMMA split-bf16 GEMM ----------------
#define PARTA (128*48)
#define PARTB (64*48)
#define GW_SMEM(NS) ((NS)*(PARTA+PARTB)*2)

template<int NS>
__global__ void __launch_bounds__(256) gemm_wmma_kernel(
    const __nv_bfloat16* __restrict__ A0, const __nv_bfloat16* __restrict__ A1,
    const __nv_bfloat16* __restrict__ A2,
    const __nv_bfloat16* __restrict__ B0, const __nv_bfloat16* __restrict__ B1,
    const __nv_bfloat16* __restrict__ B2,
    float* __restrict__ C, int scatter)
{
    extern __shared__ __nv_bfloat16 smw[];
    __nv_bfloat16* As = smw;
    __nv_bfloat16* Bs = smw + NS*PARTA;
    int tid = threadIdx.x;
    int wid = tid >> 5;
    int wm = wid & 3, wn = wid >> 2;
    int row0 = blockIdx.y * 128, col0 = blockIdx.x * 64;

    const __nv_bfloat16* aps[3];
    const __nv_bfloat16* bps[3];
    aps[0] = A0; aps[1] = A1; aps[2] = (NS > 2) ? A2 : A0;
    bps[0] = B0; bps[1] = B1; bps[2] = (NS > 2) ? B2 : B0;

    wmma::fragment<wmma::accumulator, 16, 16, 16, float> acc[2][2];
#pragma unroll
    for (int i = 0; i < 2; ++i)
#pragma unroll
        for (int j = 0; j < 2; ++j) wmma::fill_fragment(acc[i][j], 0.0f);

    int ar0 = (tid * 2) >> 2,  ac0 = ((tid * 2) & 3) * 8;
    int ar1 = (tid * 2 + 1) >> 2, ac1 = ((tid * 2 + 1) & 3) * 8;
    int br = tid >> 2, bc = (tid & 3) * 8;

    for (int kb = 0; kb < DD; kb += 32) {
        __syncthreads();
#pragma unroll
        for (int p = 0; p < NS; ++p) {
            *(uint4*)(As + p*PARTA + ar0*48 + ac0) =
                *(const uint4*)(aps[p] + (size_t)(row0 + ar0)*DD + kb + ac0);
            *(uint4*)(As + p*PARTA + ar1*48 + ac1) =
                *(const uint4*)(aps[p] + (size_t)(row0 + ar1)*DD + kb + ac1);
            *(uint4*)(Bs + p*PARTB + br*48 + bc) =
                *(const uint4*)(bps[p] + (size_t)(col0 + br)*DD + kb + bc);
        }
        __syncthreads();
#pragma unroll
        for (int ks = 0; ks < 32; ks += 16) {
#pragma unroll
            for (int pi = 0; pi < NS; ++pi) {
#pragma unroll
                for (int pj = 0; pj < NS; ++pj) {
                    if (pi + pj >= NS) continue;
                    wmma::fragment<wmma::matrix_a, 16, 16, 16, __nv_bfloat16, wmma::row_major> af[2];
                    wmma::fragment<wmma::matrix_b, 16, 16, 16, __nv_bfloat16, wmma::col_major> bf[2];
                    wmma::load_matrix_sync(af[0], As + pi*PARTA + (wm*32 +  0)*48 + ks, 48);
                    wmma::load_matrix_sync(af[1], As + pi*PARTA + (wm*32 + 16)*48 + ks, 48);
                    wmma::load_matrix_sync(bf[0], Bs + pj*PARTB + (wn*32 +  0)*48 + ks, 48);
                    wmma::load_matrix_sync(bf[1], Bs + pj*PARTB + (wn*32 + 16)*48 + ks, 48);
#pragma unroll
                    for (int mi = 0; mi < 2; ++mi)
#pragma unroll
                        for (int ni = 0; ni < 2; ++ni)
                            wmma::mma_sync(acc[mi][ni], af[mi], bf[ni], acc[mi][ni]);
                }
            }
        }
    }

#pragma unroll
    for (int mi = 0; mi < 2; ++mi)
#pragma unroll
        for (int ni = 0; ni < 2; ++ni) {
            int r = row0 + wm*32 + mi*16;
            int c = col0 + wn*32 + ni*16;
            if (!scatter) {
                wmma::store_matrix_sync(C + (size_t)r*DD + c, acc[mi][ni], DD, wmma::mem_row_major);
            } else {
                int b = r >> 11, nrow = r & (NN - 1);
                int h = c >> 6,  dh = c & (DH - 1);
                wmma::store_matrix_sync(C + (((size_t)b*HH + h)*NN + nrow)*DH + dh,
                                        acc[mi][ni], DH, wmma::mem_row_major);
            }
        }
}

// ---------------- LayerNorm + head scatter ----------------
__global__ void __launch_bounds__(256) ln_scatter_kernel(
    const float* __restrict__ Y, const float* __restrict__ gam,
    const float* __restrict__ bet, float* __restrict__ O)
{
    int row = blockIdx.x, t = threadIdx.x;
    const float* y = Y + (size_t)row * DD;
    float x0 = y[t], x1 = y[t+256], x2 = y[t+512], x3 = y[t+768];
    float s = x0+x1+x2+x3;
    float q = x0*x0 + x1*x1 + x2*x2 + x3*x3;
#pragma unroll
    for (int off = 16; off; off >>= 1) {
        s += __shfl_xor_sync(0xffffffffu, s, off);
        q += __shfl_xor_sync(0xffffffffu, q, off);
    }
    __shared__ float ss[8], sq[8];
    __shared__ float smu, srstd;
    if ((t & 31) == 0) { ss[t>>5] = s; sq[t>>5] = q; }
    __syncthreads();
    if (t == 0) {
        float S = 0.f, Q = 0.f;
#pragma unroll
        for (int i = 0; i < 8; ++i) { S += ss[i]; Q += sq[i]; }
        float mu = S * (1.0f/DD);
        float var = Q * (1.0f/DD) - mu*mu;
        smu = mu; srstd = rsqrtf(var + 1e-5f);
    }
    __syncthreads();
    float mu = smu, rs = srstd;
    int b = row >> 11, n = row & (NN-1);
    float xs[4] = {x0, x1, x2, x3};
#pragma unroll
    for (int i = 0; i < 4; ++i) {
        int d = t + i*256;
        float v = (xs[i] - mu) * rs * gam[d] + bet[d];
        O[(((size_t)b*HH + (d>>6))*NN + n)*DH + (d & (DH-1))] = v;
    }
}

// ---------------- S0 (fp32 selection path, unchanged) ----------------
__global__ void __launch_bounds__(256) s0_kernel(
    const float* __restrict__ Qv, const float* __restrict__ Kv, float* __restrict__ S0)
{
    int b  = blockIdx.z;
    int j0 = blockIdx.y << 6, m0 = blockIdx.x << 6;
    int tid = threadIdx.x;
    size_t outbase = ((size_t)b*NN + j0)*MM + m0;
    if (m0 >= j0 + 64) {
        for (int idx = tid; idx < 4096; idx += 256) {
            int jj = idx >> 6, mm = idx & 63;
            S0[outbase + (size_t)jj*MM + mm] = 0.f;
        }
        return;
    }
    __shared__ float Qs[64][68];
    __shared__ float Kts[64][64];
    const float* Qb = Qv + (((size_t)b*HH + 0)*NN + j0)*DH;
    const float* Kb = Kv + (((size_t)b*HH + 0)*NN + m0)*DH;
    int r = tid >> 2, c0 = (tid & 3) << 4;
#pragma unroll
    for (int u = 0; u < 4; ++u) {
        float4 v = *(const float4*)(Qb + (size_t)r*DH + c0 + u*4);
        Qs[r][c0+u*4+0] = v.x; Qs[r][c0+u*4+1] = v.y; Qs[r][c0+u*4+2] = v.z; Qs[r][c0+u*4+3] = v.w;
        float4 w = *(const float4*)(Kb + (size_t)r*DH + c0 + u*4);
        Kts[c0+u*4+0][r] = w.x; Kts[c0+u*4+1][r] = w.y; Kts[c0+u*4+2][r] = w.z; Kts[c0+u*4+3][r] = w.w;
    }
    __syncthreads();
    int tx = tid & 15, ty = tid >> 4;
    float acc[4][4] = {};
#pragma unroll 8
    for (int k = 0; k < 64; ++k) {
        float a0 = Qs[ty*4+0][k], a1 = Qs[ty*4+1][k];
        float a2 = Qs[ty*4+2][k], a3 = Qs[ty*4+3][k];
        float4 b4 = *(const float4*)&Kts[k][tx*4];
        acc[0][0] += a0*b4.x; acc[0][1] += a0*b4.y; acc[0][2] += a0*b4.z; acc[0][3] += a0*b4.w;
        acc[1][0] += a1*b4.x; acc[1][1] += a1*b4.y; acc[1][2] += a1*b4.z; acc[1][3] += a1*b4.w;
        acc[2][0] += a2*b4.x; acc[2][1] += a2*b4.y; acc[2][2] += a2*b4.z; acc[2][3] += a2*b4.w;
        acc[3][0] += a3*b4.x; acc[3][1] += a3*b4.y; acc[3][2] += a3*b4.z; acc[3][3] += a3*b4.w;
    }
#pragma unroll
    for (int i = 0; i < 4; ++i) {
        int j = j0 + ty*4 + i;
        int mb = m0 + tx*4;
        float4 w;
        w.x = ((mb+0) == 0 || (mb+0) >= j) ? 0.f : fmaxf(acc[i][0]*0.125f, 0.f);
        w.y = ((mb+1) == 0 || (mb+1) >= j) ? 0.f : fmaxf(acc[i][1]*0.125f, 0.f);
        w.z = ((mb+2) == 0 || (mb+2) >= j) ? 0.f : fmaxf(acc[i][2]*0.125f, 0.f);
        w.w = ((mb+3) == 0 || (mb+3) >= j) ? 0.f : fmaxf(acc[i][3]*0.125f, 0.f);
        *(float4*)(S0 + ((size_t)b*NN + j)*MM + mb) = w;
    }
}

// ---------------- Finit ----------------
__global__ void __launch_bounds__(256) finit_kernel(
    const float* __restrict__ S0, float* __restrict__ Fi)
{
    int b = blockIdx.y;
    int col = (blockIdx.x << 6) + (threadIdx.x & 63);
    int part = threadIdx.x >> 6;
    const float* base = S0 + ((size_t)b*NN + part*256)*MM + col;
    float s = 0.f;
#pragma unroll 4
    for (int r = 0; r < 256; ++r) s += base[(size_t)r*MM];
    __shared__ float ps[256];
    ps[threadIdx.x] = s;
    __syncthreads();
    if (threadIdx.x < 64) {
        Fi[b*MM + (blockIdx.x << 6) + threadIdx.x] =
            ps[threadIdx.x] + ps[threadIdx.x+64] + ps[threadIdx.x+128] + ps[threadIdx.x+192];
    }
}

// ---------------- serial eviction scan ----------------
__global__ void __launch_bounds__(1024) scan_kernel(
    const float* __restrict__ S0, const float* __restrict__ Fi, int* __restrict__ evict)
{
    __shared__ float F[2048];
    __shared__ int unm[1024];
    __shared__ float wv[32];
    __shared__ int wp[32];
    __shared__ int s_idx;
    int b = blockIdx.x, t = threadIdx.x;
    F[t]        = Fi[b*MM + t];
    F[t + 1024] = Fi[b*MM + 1024 + t];
    unm[t] = t;
    evict[b*MM + t] = BIGV;
    evict[b*MM + 1024 + t] = BIGV;
    const float* Sb = S0 + (size_t)b*NN*MM;
    float r0 = 0.f, r1 = 0.f;
    __syncthreads();
    for (int i = 1024; i < 2048; ++i) {
        F[t]        += r0;
        F[t + 1024] += r1;
        const float* nrow = Sb + (size_t)i*MM;
        r0 = nrow[t]; r1 = nrow[t + 1024];
        __syncthreads();
        float v = F[unm[t]];
        int   p = t;
#pragma unroll
        for (int off = 16; off; off >>= 1) {
            float ov = __shfl_down_sync(0xffffffffu, v, off);
            int   op = __shfl_down_sync(0xffffffffu, p, off);
            if (ov > v || (ov == v && op < p)) { v = ov; p = op; }
        }
        if ((t & 31) == 0) { wv[t>>5] = v; wp[t>>5] = p; }
        __syncthreads();
        if (t < 32) {
            v = wv[t]; p = wp[t];
#pragma unroll
            for (int off = 16; off; off >>= 1) {
                float ov = __shfl_down_sync(0xffffffffu, v, off);
                int   op = __shfl_down_sync(0xffffffffu, p, off);
                if (ov > v || (ov == v && op < p)) { v = ov; p = op; }
            }
            if (t == 0) s_idx = p;
        }
        __syncthreads();
        int idx = s_idx;
        if (t == idx) evict[b*MM + unm[idx]] = i;
        int nv = (t < idx) ? unm[t] : (t < 1023 ? unm[t+1] : i);
        __syncthreads();
        unm[t] = nv;
        __syncthreads();
    }
}

// ---------------- WMMA flash attention (split bf16, no online softmax) ----------------
// Logits are ~N(0,1) (LN'd inputs, 1/sqrt(Dh) scale), max ~6 << 88, so exp() cannot
// overflow fp32 without max subtraction -> output accumulators stay in persistent frags.
#define AT_LDB 72
#define AT_LDS 68
#define ATT2_SMEM (8*64*AT_LDB*2 + 64*AT_LDS*4 + 64*4)

__global__ void __launch_bounds__(256) attn_wmma_kernel(
    const float* __restrict__ Qv, const float* __restrict__ Kv,
    const float* __restrict__ Vv, const int* __restrict__ ev_g,
    float* __restrict__ AO)
{
    extern __shared__ char smc[];
    __nv_bfloat16* Qh = (__nv_bfloat16*)smc;
    __nv_bfloat16* Qm = Qh + 64*AT_LDB;
    __nv_bfloat16* Kh = Qm + 64*AT_LDB;
    __nv_bfloat16* Km = Kh + 64*AT_LDB;
    __nv_bfloat16* Vh = Km + 64*AT_LDB;
    __nv_bfloat16* Vm = Vh + 64*AT_LDB;
    __nv_bfloat16* Ph = Vm + 64*AT_LDB;
    __nv_bfloat16* Pm = Ph + 64*AT_LDB;
    float* Ps = (float*)(Pm + 64*AT_LDB);
    int*   evs = (int*)(Ps + 64*AT_LDS);

    int bq = (int)gridDim.x - 1 - (int)blockIdx.x;   // heavy tiles first
    int h = blockIdx.y, b = blockIdx.z;
    int nq0 = bq << 6;
    int tid = threadIdx.x;
    int wid = tid >> 5;
    int tx = tid & 15, ty = tid >> 4;
    int wm = wid & 3, wn = wid >> 2;                 // 4 x 2 warp grid

    // load + split Q tile
    {
        const float* Qb = Qv + (((size_t)b*HH + h)*NN + nq0)*DH;
        int r = tid >> 2, c0 = (tid & 3) << 4;
#pragma unroll
        for (int u = 0; u < 4; ++u) {
            float4 v = *(const float4*)(Qb + (size_t)r*DH + c0 + u*4);
            float vv[4] = {v.x, v.y, v.z, v.w};
#pragma unroll
            for (int e = 0; e < 4; ++e) {
                int c = c0 + u*4 + e;
                __nv_bfloat16 hh = __float2bfloat16(vv[e]);
                Qh[r*AT_LDB + c] = hh;
                Qm[r*AT_LDB + c] = __float2bfloat16(vv[e] - __bfloat162float(hh));
            }
        }
    }

    wmma::fragment<wmma::accumulator, 16, 16, 16, float> oacc[2];
#pragma unroll
    for (int ni = 0; ni < 2; ++ni) wmma::fill_fragment(oacc[ni], 0.0f);
    float lrow[4] = {0.f, 0.f, 0.f, 0.f};

    for (int kt = 0; kt <= bq; ++kt) {
        int m0 = kt << 6;
        __syncthreads();   // prior PV reads of Kh/Km/Vh/Vm done
        {
            const float* Kb = Kv + (((size_t)b*HH + h)*NN + m0)*DH;
            const float* Vb = Vv + (((size_t)b*HH + h)*NN + m0)*DH;
            int r = tid >> 2, c0 = (tid & 3) << 4;
#pragma unroll
            for (int u = 0; u < 4; ++u) {
                float4 v = *(const float4*)(Kb + (size_t)r*DH + c0 + u*4);
                float4 w = *(const float4*)(Vb + (size_t)r*DH + c0 + u*4);
                float kv[4] = {v.x, v.y, v.z, v.w};
                float vv[4] = {w.x, w.y, w.z, w.w};
#pragma unroll
                for (int e = 0; e < 4; ++e) {
                    int c = c0 + u*4 + e;
                    __nv_bfloat16 kh = __float2bfloat16(kv[e]);
                    Kh[r*AT_LDB + c] = kh;
                    Km[r*AT_LDB + c] = __float2bfloat16(kv[e] - __bfloat162float(kh));
                    __nv_bfloat16 vh = __float2bfloat16(vv[e]);
                    Vh[r*AT_LDB + c] = vh;
                    Vm[r*AT_LDB + c] = __float2bfloat16(vv[e] - __bfloat162float(vh));
                }
            }
            if (tid < 64) evs[tid] = ev_g[b*MM + m0 + tid];
        }
        __syncthreads();

        // S = Q K^T via 3 split products
        wmma::fragment<wmma::accumulator, 16, 16, 16, float> sacc[2];
#pragma unroll
        for (int ni = 0; ni < 2; ++ni) wmma::fill_fragment(sacc[ni], 0.0f);
#pragma unroll
        for (int ks = 0; ks < 4; ++ks) {
            wmma::fragment<wmma::matrix_a, 16, 16, 16, __nv_bfloat16, wmma::row_major> ah, am;
            wmma::load_matrix_sync(ah, Qh + (wm*16)*AT_LDB + ks*16, AT_LDB);
            wmma::load_matrix_sync(am, Qm + (wm*16)*AT_LDB + ks*16, AT_LDB);
#pragma unroll
            for (int ni = 0; ni < 2; ++ni) {
                wmma::fragment<wmma::matrix_b, 16, 16, 16, __nv_bfloat16, wmma::col_major> bh, bm;
                wmma::load_matrix_sync(bh, Kh + (wn*32 + ni*16)*AT_LDB + ks*16, AT_LDB);
                wmma::load_matrix_sync(bm, Km + (wn*32 + ni*16)*AT_LDB + ks*16, AT_LDB);
                wmma::mma_sync(sacc[ni], ah, bh, sacc[ni]);
                wmma::mma_sync(sacc[ni], am, bh, sacc[ni]);
                wmma::mma_sync(sacc[ni], ah, bm, sacc[ni]);
            }
        }
#pragma unroll
        for (int ni = 0; ni < 2; ++ni)
            wmma::store_matrix_sync(Ps + (wm*16)*AT_LDS + wn*32 + ni*16, sacc[ni],
                                    AT_LDS, wmma::mem_row_major);
        __syncthreads();

        // mask + exp + den accumulate + split P to bf16
        int ev4[4];
#pragma unroll
        for (int j = 0; j < 4; ++j) ev4[j] = evs[tx*4 + j];
#pragma unroll
        for (int i = 0; i < 4; ++i) {
            int n = nq0 + ty*4 + i;
            float rsum = 0.f;
#pragma unroll
            for (int j = 0; j < 4; ++j) {
                int m = m0 + tx*4 + j;
                float s = Ps[(ty*4+i)*AT_LDS + tx*4 + j];
                bool keep = (m <= n) && (n < ev4[j]);
                float pv = keep ? __expf(s * 0.125f) : 0.f;
                __nv_bfloat16 ph = __float2bfloat16(pv);
                Ph[(ty*4+i)*AT_LDB + tx*4 + j] = ph;
                Pm[(ty*4+i)*AT_LDB + tx*4 + j] = __float2bfloat16(pv - __bfloat162float(ph));
                rsum += pv;
            }
#pragma unroll
            for (int off = 8; off; off >>= 1) rsum += __shfl_xor_sync(0xffffffffu, rsum, off);
            lrow[i] += rsum;
        }
        __syncthreads();

        // O += P V via 3 split products (persistent accumulators, no rescale)
#pragma unroll
        for (int ks = 0; ks < 4; ++ks) {
            wmma::fragment<wmma::matrix_a, 16, 16, 16, __nv_bfloat16, wmma::row_major> pah, pam;
            wmma::load_matrix_sync(pah, Ph + (wm*16)*AT_LDB + ks*16, AT_LDB);
            wmma::load_matrix_sync(pam, Pm + (wm*16)*AT_LDB + ks*16, AT_LDB);
#pragma unroll
            for (int ni = 0; ni < 2; ++ni) {
                wmma::fragment<wmma::matrix_b, 16, 16, 16, __nv_bfloat16, wmma::row_major> vbh, vbm;
                wmma::load_matrix_sync(vbh, Vh + (ks*16)*AT_LDB + wn*32 + ni*16, AT_LDB);
                wmma::load_matrix_sync(vbm, Vm + (ks*16)*AT_LDB + wn*32 + ni*16, AT_LDB);
                wmma::mma_sync(oacc[ni], pah, vbh, oacc[ni]);
                wmma::mma_sync(oacc[ni], pah, vbm, oacc[ni]);
                wmma::mma_sync(oacc[ni], pam, vbh, oacc[ni]);
            }
        }
    }

    __syncthreads();
#pragma unroll
    for (int ni = 0; ni < 2; ++ni)
        wmma::store_matrix_sync(Ps + (wm*16)*AT_LDS + wn*32 + ni*16, oacc[ni],
                                AT_LDS, wmma::mem_row_major);
    __syncthreads();
#pragma unroll
    for (int i = 0; i < 4; ++i) {
        float rl = 1.0f / lrow[i];
        int n = nq0 + ty*4 + i;
        const float* pr = Ps + (ty*4+i)*AT_LDS + tx*4;
        float4 w = make_float4(pr[0]*rl, pr[1]*rl, pr[2]*rl, pr[3]*rl);
        *(float4*)(AO + ((size_t)b*NN + n)*DD + h*DH + tx*4) = w;
    }
}

extern "C" void kernel_launch(void* const* d_in, const int* in_sizes, int n_in,
                              void* d_out, int out_size)
{
    (void)in_sizes; (void)n_in; (void)out_size;
    const float* X  = (const float*)d_in[0];
    const float* Wq = (const float*)d_in[1];
    const float* Wk = (const float*)d_in[2];
    const float* Wv = (const float*)d_in[3];
    const float* Wo = (const float*)d_in[4];
    const float* gq = (const float*)d_in[5];
    const float* bq = (const float*)d_in[6];
    const float* gk = (const float*)d_in[7];
    const float* bk = (const float*)d_in[8];
    float* out = (float*)d_out;

    float *Yq, *Yk, *Qp, *Kp, *Vp, *S0, *Fi, *AO; int* ev;
    cudaGetSymbolAddress((void**)&Yq, g_Yq);
    cudaGetSymbolAddress((void**)&Yk, g_Yk);
    cudaGetSymbolAddress((void**)&Qp, g_Q);
    cudaGetSymbolAddress((void**)&Kp, g_K);
    cudaGetSymbolAddress((void**)&Vp, g_V);
    cudaGetSymbolAddress((void**)&S0, g_S0);
    cudaGetSymbolAddress((void**)&Fi, g_Fi);
    cudaGetSymbolAddress((void**)&ev, g_ev);
    cudaGetSymbolAddress((void**)&AO, g_AO);
    __nv_bfloat16 *Xh,*Xm,*Xl,*Wqh,*Wqm,*Wql,*Wkh,*Wkm,*Wkl,*Wvh,*Wvm,*Woh,*Wom,*Ah,*Am;
    cudaGetSymbolAddress((void**)&Xh, g_Xh);  cudaGetSymbolAddress((void**)&Xm, g_Xm);
    cudaGetSymbolAddress((void**)&Xl, g_Xl);
    cudaGetSymbolAddress((void**)&Wqh, g_Wqh); cudaGetSymbolAddress((void**)&Wqm, g_Wqm);
    cudaGetSymbolAddress((void**)&Wql, g_Wql);
    cudaGetSymbolAddress((void**)&Wkh, g_Wkh); cudaGetSymbolAddress((void**)&Wkm, g_Wkm);
    cudaGetSymbolAddress((void**)&Wkl, g_Wkl);
    cudaGetSymbolAddress((void**)&Wvh, g_Wvh); cudaGetSymbolAddress((void**)&Wvm, g_Wvm);
    cudaGetSymbolAddress((void**)&Woh, g_Woh); cudaGetSymbolAddress((void**)&Wom, g_Wom);
    cudaGetSymbolAddress((void**)&Ah, g_Ah);   cudaGetSymbolAddress((void**)&Am, g_Am);

    cudaFuncSetAttribute(attn_wmma_kernel, cudaFuncAttributeMaxDynamicSharedMemorySize, ATT2_SMEM);
    cudaFuncSetAttribute(gemm_wmma_kernel<3>, cudaFuncAttributeMaxDynamicSharedMemorySize, GW_SMEM(3));
    cudaFuncSetAttribute(gemm_wmma_kernel<2>, cudaFuncAttributeMaxDynamicSharedMemorySize, GW_SMEM(2));

    dim3 wgrid(32, 32);
    dim3 ggrid(DD/64, RR/128);

    conv3_kernel<<<RR*DD/256, 256>>>(X, Xh, Xm, Xl);
    convW_kernel<<<wgrid, dim3(32,8)>>>(Wq, Wqh, Wqm, Wql);
    convW_kernel<<<wgrid, dim3(32,8)>>>(Wk, Wkh, Wkm, Wkl);
    convW_kernel<<<wgrid, dim3(32,8)>>>(Wv, Wvh, Wvm, nullptr);
    convW_kernel<<<wgrid, dim3(32,8)>>>(Wo, Woh, Wom, nullptr);
    gemm_wmma_kernel<3><<<ggrid, 256, GW_SMEM(3)>>>(Xh, Xm, Xl, Wqh, Wqm, Wql, Yq, 0);
    gemm_wmma_kernel<3><<<ggrid, 256, GW_SMEM(3)>>>(Xh, Xm, Xl, Wkh, Wkm, Wkl, Yk, 0);
    gemm_wmma_kernel<2><<<ggrid, 256, GW_SMEM(2)>>>(Xh, Xm, nullptr, Wvh, Wvm, nullptr, Vp, 1);
    ln_scatter_kernel<<<RR, 256>>>(Yq, gq, bq, Qp);
    ln_scatter_kernel<<<RR, 256>>>(Yk, gk, bk, Kp);
    s0_kernel<<<dim3(MM/64, NN/64, BB), 256>>>(Qp, Kp, S0);
    finit_kernel<<<dim3(MM/64, BB), 256>>>(S0, Fi);
    scan_kernel<<<BB, 1024>>>(S0, Fi, ev);
    attn_wmma_kernel<<<dim3(NN/64, HH, BB), 256, ATT2_SMEM>>>(Qp, Kp, Vp, ev, AO);
    conv3_kernel<<<RR*DD/256, 256>>>(AO, Ah, Am, nullptr);
    gemm_wmma_kernel<2><<<ggrid, 256, GW_SMEM(2)>>>(Ah, Am, nullptr, Woh, Wom, nullptr, out, 0);
}

// round 6
// speedup vs baseline: 1.3289x; 1.1678x over previous
#include <cuda_runtime.h>
#include <cuda_bf16.h>
#include <cuda_fp16.h>
#include <mma.h>
#include <cstdint>
#include <cstddef>

using namespace nvcuda;

#define BB 2
#define NN 2048
#define DD 1024
#define HH 16
#define DH 64
#define RR (BB*NN)
#define MM 2048
#define BIGV (1<<30)

// ---------------- scratch ----------------
__device__ float g_Yq[(size_t)RR*DD];
__device__ float g_Yk[(size_t)RR*DD];
__device__ float g_Q[(size_t)BB*HH*NN*DH];
__device__ float g_K[(size_t)BB*HH*NN*DH];
__device__ float g_V[(size_t)BB*HH*NN*DH];
__device__ float g_S0[(size_t)BB*NN*MM];
__device__ float g_Fi[BB*MM];
__device__ int   g_ev[BB*MM];
__device__ float g_AO[(size_t)RR*DD];
// fp16 2-split operands
__device__ __half g_hXa[(size_t)RR*DD], g_hXb[(size_t)RR*DD];
__device__ __half g_hWqa[(size_t)DD*DD], g_hWqb[(size_t)DD*DD];
__device__ __half g_hWka[(size_t)DD*DD], g_hWkb[(size_t)DD*DD];
__device__ __half g_hWva[(size_t)DD*DD], g_hWvb[(size_t)DD*DD];
__device__ __half g_hWoa[(size_t)DD*DD], g_hWob[(size_t)DD*DD];
__device__ __half g_hAa[(size_t)RR*DD], g_hAb[(size_t)RR*DD];

// ---------------- conversions (fp16 2-split) ----------------
__global__ void __launch_bounds__(256) conv2h_kernel(
    const float* __restrict__ X, __half* __restrict__ H, __half* __restrict__ M)
{
    int i = blockIdx.x * 256 + threadIdx.x;
    float v = X[i];
    __half h = __float2half_rn(v);
    M[i] = __float2half_rn(v - __half2float(h));
    H[i] = h;
}

// transpose + 2-split: T*[n][k] = split(W[k][n])
__global__ void __launch_bounds__(256) convW2h_kernel(
    const float* __restrict__ W, __half* __restrict__ TH, __half* __restrict__ TM)
{
    __shared__ float tile[32][33];
    int n0 = blockIdx.x * 32, k0 = blockIdx.y * 32;
    int tx = threadIdx.x, ty = threadIdx.y;   // 32 x 8
#pragma unroll
    for (int i = 0; i < 32; i += 8)
        tile[ty + i][tx] = W[(size_t)(k0 + ty + i) * DD + n0 + tx];
    __syncthreads();
#pragma unroll
    for (int i = 0; i < 32; i += 8) {
        float v = tile[tx][ty + i];
        __half h = __float2half_rn(v);
        size_t o = (size_t)(n0 + ty + i) * DD + k0 + tx;
        TH[o] = h;
        TM[o] = __float2half_rn(v - __half2float(h));
    }
}

// ---------------- fp16 2-split WMMA GEMM, double-buffered ----------------
// C = (A0+A1)(B0+B1) ~= A0B0 + A0B1 + A1B0 ; error ~2^-22.
// Block 128x64, 8 warps (4m x 2n), warp tile 32x32, BK=32, 2 smem buffers.
#define HPARTA (128*48)
#define HPARTB (64*48)
#define HBUF   (2*HPARTA + 2*HPARTB)
#define GH_SMEM (2*HBUF*2)

__global__ void __launch_bounds__(256) gemm_h2_kernel(
    const __half* __restrict__ A0, const __half* __restrict__ A1,
    const __half* __restrict__ B0, const __half* __restrict__ B1,
    float* __restrict__ C, int scatter)
{
    extern __shared__ __half smh[];
    int tid = threadIdx.x, wid = tid >> 5;
    int wm = wid & 3, wn = wid >> 2;
    int row0 = blockIdx.y * 128, col0 = blockIdx.x * 64;

    const __half* ap[2] = { A0 + (size_t)row0 * DD, A1 + (size_t)row0 * DD };
    const __half* bp[2] = { B0 + (size_t)col0 * DD, B1 + (size_t)col0 * DD };

    int ar0 = (tid * 2) >> 2,     ac0 = ((tid * 2) & 3) * 8;
    int ar1 = (tid * 2 + 1) >> 2, ac1 = ((tid * 2 + 1) & 3) * 8;
    int br  = tid >> 2,           bc  = (tid & 3) * 8;

    wmma::fragment<wmma::accumulator, 16, 16, 16, float> acc[2][2];
#pragma unroll
    for (int i = 0; i < 2; ++i)
#pragma unroll
        for (int j = 0; j < 2; ++j) wmma::fill_fragment(acc[i][j], 0.0f);

    uint4 ra[2][2], rb[2];

#define LOADG(KB) do { \
    ra[0][0] = *(const uint4*)(ap[0] + (size_t)ar0*DD + (KB) + ac0); \
    ra[0][1] = *(const uint4*)(ap[0] + (size_t)ar1*DD + (KB) + ac1); \
    rb[0]    = *(const uint4*)(bp[0] + (size_t)br *DD + (KB) + bc ); \
    ra[1][0] = *(const uint4*)(ap[1] + (size_t)ar0*DD + (KB) + ac0); \
    ra[1][1] = *(const uint4*)(ap[1] + (size_t)ar1*DD + (KB) + ac1); \
    rb[1]    = *(const uint4*)(bp[1] + (size_t)br *DD + (KB) + bc ); \
} while (0)

#define STORES(BUF) do { \
    __half* _b = smh + (BUF)*HBUF; \
    *(uint4*)(_b + 0*HPARTA + ar0*48 + ac0) = ra[0][0]; \
    *(uint4*)(_b + 0*HPARTA + ar1*48 + ac1) = ra[0][1]; \
    *(uint4*)(_b + 1*HPARTA + ar0*48 + ac0) = ra[1][0]; \
    *(uint4*)(_b + 1*HPARTA + ar1*48 + ac1) = ra[1][1]; \
    *(uint4*)(_b + 2*HPARTA + 0*HPARTB + br*48 + bc) = rb[0]; \
    *(uint4*)(_b + 2*HPARTA + 1*HPARTB + br*48 + bc) = rb[1]; \
} while (0)

    LOADG(0);
    STORES(0);
    __syncthreads();

    for (int kt = 0; kt < 32; ++kt) {
        if (kt + 1 < 32) LOADG((kt + 1) * 32);
        __half* Asb = smh + (kt & 1) * HBUF;
        __half* Bsb = Asb + 2 * HPARTA;
#pragma unroll
        for (int ks = 0; ks < 2; ++ks) {
            wmma::fragment<wmma::matrix_a, 16, 16, 16, __half, wmma::row_major> a0f[2], a1f[2];
            wmma::fragment<wmma::matrix_b, 16, 16, 16, __half, wmma::col_major> b0f[2], b1f[2];
#pragma unroll
            for (int mi = 0; mi < 2; ++mi) {
                wmma::load_matrix_sync(a0f[mi], Asb + 0*HPARTA + (wm*32 + mi*16)*48 + ks*16, 48);
                wmma::load_matrix_sync(a1f[mi], Asb + 1*HPARTA + (wm*32 + mi*16)*48 + ks*16, 48);
            }
#pragma unroll
            for (int ni = 0; ni < 2; ++ni) {
                wmma::load_matrix_sync(b0f[ni], Bsb + 0*HPARTB + (wn*32 + ni*16)*48 + ks*16, 48);
                wmma::load_matrix_sync(b1f[ni], Bsb + 1*HPARTB + (wn*32 + ni*16)*48 + ks*16, 48);
            }
#pragma unroll
            for (int mi = 0; mi < 2; ++mi)
#pragma unroll
                for (int ni = 0; ni < 2; ++ni) {
                    wmma::mma_sync(acc[mi][ni], a0f[mi], b0f[ni], acc[mi][ni]);
                    wmma::mma_sync(acc[mi][ni], a0f[mi], b1f[ni], acc[mi][ni]);
                    wmma::mma_sync(acc[mi][ni], a1f[mi], b0f[ni], acc[mi][ni]);
                }
        }
        __syncthreads();
        if (kt + 1 < 32) { STORES((kt + 1) & 1); __syncthreads(); }
    }
#undef LOADG
#undef STORES

#pragma unroll
    for (int mi = 0; mi < 2; ++mi)
#pragma unroll
        for (int ni = 0; ni < 2; ++ni) {
            int r = row0 + wm*32 + mi*16;
            int c = col0 + wn*32 + ni*16;
            if (!scatter) {
                wmma::store_matrix_sync(C + (size_t)r*DD + c, acc[mi][ni], DD, wmma::mem_row_major);
            } else {
                int b = r >> 11, nrow = r & (NN - 1);
                int h = c >> 6,  dh = c & (DH - 1);
                wmma::store_matrix_sync(C + (((size_t)b*HH + h)*NN + nrow)*DH + dh,
                                        acc[mi][ni], DH, wmma::mem_row_major);
            }
        }
}

// ---------------- LayerNorm + head scatter ----------------
__global__ void __launch_bounds__(256) ln_scatter_kernel(
    const float* __restrict__ Y, const float* __restrict__ gam,
    const float* __restrict__ bet, float* __restrict__ O)
{
    int row = blockIdx.x, t = threadIdx.x;
    const float* y = Y + (size_t)row * DD;
    float x0 = y[t], x1 = y[t+256], x2 = y[t+512], x3 = y[t+768];
    float s = x0+x1+x2+x3;
    float q = x0*x0 + x1*x1 + x2*x2 + x3*x3;
#pragma unroll
    for (int off = 16; off; off >>= 1) {
        s += __shfl_xor_sync(0xffffffffu, s, off);
        q += __shfl_xor_sync(0xffffffffu, q, off);
    }
    __shared__ float ss[8], sq[8];
    __shared__ float smu, srstd;
    if ((t & 31) == 0) { ss[t>>5] = s; sq[t>>5] = q; }
    __syncthreads();
    if (t == 0) {
        float S = 0.f, Q = 0.f;
#pragma unroll
        for (int i = 0; i < 8; ++i) { S += ss[i]; Q += sq[i]; }
        float mu = S * (1.0f/DD);
        float var = Q * (1.0f/DD) - mu*mu;
        smu = mu; srstd = rsqrtf(var + 1e-5f);
    }
    __syncthreads();
    float mu = smu, rs = srstd;
    int b = row >> 11, n = row & (NN-1);
    float xs[4] = {x0, x1, x2, x3};
#pragma unroll
    for (int i = 0; i < 4; ++i) {
        int d = t + i*256;
        float v = (xs[i] - mu) * rs * gam[d] + bet[d];
        O[(((size_t)b*HH + (d>>6))*NN + n)*DH + (d & (DH-1))] = v;
    }
}

// ---------------- S0 (fp32 selection path, unchanged) ----------------
__global__ void __launch_bounds__(256) s0_kernel(
    const float* __restrict__ Qv, const float* __restrict__ Kv, float* __restrict__ S0)
{
    int b  = blockIdx.z;
    int j0 = blockIdx.y << 6, m0 = blockIdx.x << 6;
    int tid = threadIdx.x;
    size_t outbase = ((size_t)b*NN + j0)*MM + m0;
    if (m0 >= j0 + 64) {
        for (int idx = tid; idx < 4096; idx += 256) {
            int jj = idx >> 6, mm = idx & 63;
            S0[outbase + (size_t)jj*MM + mm] = 0.f;
        }
        return;
    }
    __shared__ float Qs[64][68];
    __shared__ float Kts[64][64];
    const float* Qb = Qv + (((size_t)b*HH + 0)*NN + j0)*DH;
    const float* Kb = Kv + (((size_t)b*HH + 0)*NN + m0)*DH;
    int r = tid >> 2, c0 = (tid & 3) << 4;
#pragma unroll
    for (int u = 0; u < 4; ++u) {
        float4 v = *(const float4*)(Qb + (size_t)r*DH + c0 + u*4);
        Qs[r][c0+u*4+0] = v.x; Qs[r][c0+u*4+1] = v.y; Qs[r][c0+u*4+2] = v.z; Qs[r][c0+u*4+3] = v.w;
        float4 w = *(const float4*)(Kb + (size_t)r*DH + c0 + u*4);
        Kts[c0+u*4+0][r] = w.x; Kts[c0+u*4+1][r] = w.y; Kts[c0+u*4+2][r] = w.z; Kts[c0+u*4+3][r] = w.w;
    }
    __syncthreads();
    int tx = tid & 15, ty = tid >> 4;
    float acc[4][4] = {};
#pragma unroll 8
    for (int k = 0; k < 64; ++k) {
        float a0 = Qs[ty*4+0][k], a1 = Qs[ty*4+1][k];
        float a2 = Qs[ty*4+2][k], a3 = Qs[ty*4+3][k];
        float4 b4 = *(const float4*)&Kts[k][tx*4];
        acc[0][0] += a0*b4.x; acc[0][1] += a0*b4.y; acc[0][2] += a0*b4.z; acc[0][3] += a0*b4.w;
        acc[1][0] += a1*b4.x; acc[1][1] += a1*b4.y; acc[1][2] += a1*b4.z; acc[1][3] += a1*b4.w;
        acc[2][0] += a2*b4.x; acc[2][1] += a2*b4.y; acc[2][2] += a2*b4.z; acc[2][3] += a2*b4.w;
        acc[3][0] += a3*b4.x; acc[3][1] += a3*b4.y; acc[3][2] += a3*b4.z; acc[3][3] += a3*b4.w;
    }
#pragma unroll
    for (int i = 0; i < 4; ++i) {
        int j = j0 + ty*4 + i;
        int mb = m0 + tx*4;
        float4 w;
        w.x = ((mb+0) == 0 || (mb+0) >= j) ? 0.f : fmaxf(acc[i][0]*0.125f, 0.f);
        w.y = ((mb+1) == 0 || (mb+1) >= j) ? 0.f : fmaxf(acc[i][1]*0.125f, 0.f);
        w.z = ((mb+2) == 0 || (mb+2) >= j) ? 0.f : fmaxf(acc[i][2]*0.125f, 0.f);
        w.w = ((mb+3) == 0 || (mb+3) >= j) ? 0.f : fmaxf(acc[i][3]*0.125f, 0.f);
        *(float4*)(S0 + ((size_t)b*NN + j)*MM + mb) = w;
    }
}

// ---------------- Finit ----------------
__global__ void __launch_bounds__(256) finit_kernel(
    const float* __restrict__ S0, float* __restrict__ Fi)
{
    int b = blockIdx.y;
    int col = (blockIdx.x << 6) + (threadIdx.x & 63);
    int part = threadIdx.x >> 6;
    const float* base = S0 + ((size_t)b*NN + part*256)*MM + col;
    float s = 0.f;
#pragma unroll 4
    for (int r = 0; r < 256; ++r) s += base[(size_t)r*MM];
    __shared__ float ps[256];
    ps[threadIdx.x] = s;
    __syncthreads();
    if (threadIdx.x < 64) {
        Fi[b*MM + (blockIdx.x << 6) + threadIdx.x] =
            ps[threadIdx.x] + ps[threadIdx.x+64] + ps[threadIdx.x+128] + ps[threadIdx.x+192];
    }
}

// ---------------- serial eviction scan (register-resident, 2 syncs/step) ----------------
// Resident set stays sorted, so reference tie-break == smallest position. Thread t owns
// positions t (always inserted) and 1024+t (active once i > 1024+t). Evict = set -inf.
__global__ void __launch_bounds__(1024) scan_kernel(
    const float* __restrict__ S0, const float* __restrict__ Fi, int* __restrict__ evict)
{
    __shared__ float wv[32];
    __shared__ int wp[32];
    int b = blockIdx.x, t = threadIdx.x;
    int lane = t & 31, w = t >> 5;
    float f0 = Fi[b*MM + t];
    float f1 = Fi[b*MM + 1024 + t];
    bool alive0 = true, alive1 = true;
    evict[b*MM + t] = BIGV;
    evict[b*MM + 1024 + t] = BIGV;
    const float* Sb = S0 + (size_t)b*NN*MM;
    float r0 = 0.f, r1 = 0.f;

    for (int i = 1024; i < 2048; ++i) {
        f0 += r0; f1 += r1;
        const float* nrow = Sb + (size_t)i*MM;   // row added at step i+1
        r0 = nrow[t]; r1 = nrow[t + 1024];

        float v0 = alive0 ? f0 : -1e38f;
        float v1 = (alive1 && (t < i - 1024)) ? f1 : -1e38f;
        float v; int p;
        if (v1 > v0) { v = v1; p = 1024 + t; } else { v = v0; p = t; }
#pragma unroll
        for (int off = 16; off; off >>= 1) {
            float ov = __shfl_xor_sync(0xffffffffu, v, off);
            int   op = __shfl_xor_sync(0xffffffffu, p, off);
            if (ov > v || (ov == v && op < p)) { v = ov; p = op; }
        }
        if (lane == 0) { wv[w] = v; wp[w] = p; }
        __syncthreads();
        v = wv[lane]; p = wp[lane];
#pragma unroll
        for (int off = 16; off; off >>= 1) {
            float ov = __shfl_xor_sync(0xffffffffu, v, off);
            int   op = __shfl_xor_sync(0xffffffffu, p, off);
            if (ov > v || (ov == v && op < p)) { v = ov; p = op; }
        }
        // every lane now holds the evicted position p
        if (p == t)               { alive0 = false; evict[b*MM + t] = i; }
        else if (p == 1024 + t)   { alive1 = false; evict[b*MM + 1024 + t] = i; }
        __syncthreads();   // protect wv/wp reuse
    }
}

// ---------------- WMMA flash attention (split bf16, no online softmax) ----------------
#define AT_LDB 72
#define AT_LDS 68
#define ATT2_SMEM (8*64*AT_LDB*2 + 64*AT_LDS*4 + 64*4)

__global__ void __launch_bounds__(256) attn_wmma_kernel(
    const float* __restrict__ Qv, const float* __restrict__ Kv,
    const float* __restrict__ Vv, const int* __restrict__ ev_g,
    float* __restrict__ AO)
{
    extern __shared__ char smc[];
    __nv_bfloat16* Qh = (__nv_bfloat16*)smc;
    __nv_bfloat16* Qm = Qh + 64*AT_LDB;
    __nv_bfloat16* Kh = Qm + 64*AT_LDB;
    __nv_bfloat16* Km = Kh + 64*AT_LDB;
    __nv_bfloat16* Vh = Km + 64*AT_LDB;
    __nv_bfloat16* Vm = Vh + 64*AT_LDB;
    __nv_bfloat16* Ph = Vm + 64*AT_LDB;
    __nv_bfloat16* Pm = Ph + 64*AT_LDB;
    float* Ps = (float*)(Pm + 64*AT_LDB);
    int*   evs = (int*)(Ps + 64*AT_LDS);

    int bq = (int)gridDim.x - 1 - (int)blockIdx.x;
    int h = blockIdx.y, b = blockIdx.z;
    int nq0 = bq << 6;
    int tid = threadIdx.x;
    int wid = tid >> 5;
    int tx = tid & 15, ty = tid >> 4;
    int wm = wid & 3, wn = wid >> 2;

    {
        const float* Qb = Qv + (((size_t)b*HH + h)*NN + nq0)*DH;
        int r = tid >> 2, c0 = (tid & 3) << 4;
#pragma unroll
        for (int u = 0; u < 4; ++u) {
            float4 v = *(const float4*)(Qb + (size_t)r*DH + c0 + u*4);
            float vv[4] = {v.x, v.y, v.z, v.w};
#pragma unroll
            for (int e = 0; e < 4; ++e) {
                int c = c0 + u*4 + e;
                __nv_bfloat16 hh = __float2bfloat16(vv[e]);
                Qh[r*AT_LDB + c] = hh;
                Qm[r*AT_LDB + c] = __float2bfloat16(vv[e] - __bfloat162float(hh));
            }
        }
    }

    wmma::fragment<wmma::accumulator, 16, 16, 16, float> oacc[2];
#pragma unroll
    for (int ni = 0; ni < 2; ++ni) wmma::fill_fragment(oacc[ni], 0.0f);
    float lrow[4] = {0.f, 0.f, 0.f, 0.f};

    for (int kt = 0; kt <= bq; ++kt) {
        int m0 = kt << 6;
        __syncthreads();
        {
            const float* Kb = Kv + (((size_t)b*HH + h)*NN + m0)*DH;
            const float* Vb = Vv + (((size_t)b*HH + h)*NN + m0)*DH;
            int r = tid >> 2, c0 = (tid & 3) << 4;
#pragma unroll
            for (int u = 0; u < 4; ++u) {
                float4 v = *(const float4*)(Kb + (size_t)r*DH + c0 + u*4);
                float4 w = *(const float4*)(Vb + (size_t)r*DH + c0 + u*4);
                float kv[4] = {v.x, v.y, v.z, v.w};
                float vv[4] = {w.x, w.y, w.z, w.w};
#pragma unroll
                for (int e = 0; e < 4; ++e) {
                    int c = c0 + u*4 + e;
                    __nv_bfloat16 kh = __float2bfloat16(kv[e]);
                    Kh[r*AT_LDB + c] = kh;
                    Km[r*AT_LDB + c] = __float2bfloat16(kv[e] - __bfloat162float(kh));
                    __nv_bfloat16 vh = __float2bfloat16(vv[e]);
                    Vh[r*AT_LDB + c] = vh;
                    Vm[r*AT_LDB + c] = __float2bfloat16(vv[e] - __bfloat162float(vh));
                }
            }
            if (tid < 64) evs[tid] = ev_g[b*MM + m0 + tid];
        }
        __syncthreads();

        wmma::fragment<wmma::accumulator, 16, 16, 16, float> sacc[2];
#pragma unroll
        for (int ni = 0; ni < 2; ++ni) wmma::fill_fragment(sacc[ni], 0.0f);
#pragma unroll
        for (int ks = 0; ks < 4; ++ks) {
            wmma::fragment<wmma::matrix_a, 16, 16, 16, __nv_bfloat16, wmma::row_major> ah, am;
            wmma::load_matrix_sync(ah, Qh + (wm*16)*AT_LDB + ks*16, AT_LDB);
            wmma::load_matrix_sync(am, Qm + (wm*16)*AT_LDB + ks*16, AT_LDB);
#pragma unroll
            for (int ni = 0; ni < 2; ++ni) {
                wmma::fragment<wmma::matrix_b, 16, 16, 16, __nv_bfloat16, wmma::col_major> bh, bm;
                wmma::load_matrix_sync(bh, Kh + (wn*32 + ni*16)*AT_LDB + ks*16, AT_LDB);
                wmma::load_matrix_sync(bm, Km + (wn*32 + ni*16)*AT_LDB + ks*16, AT_LDB);
                wmma::mma_sync(sacc[ni], ah, bh, sacc[ni]);
                wmma::mma_sync(sacc[ni], am, bh, sacc[ni]);
                wmma::mma_sync(sacc[ni], ah, bm, sacc[ni]);
            }
        }
#pragma unroll
        for (int ni = 0; ni < 2; ++ni)
            wmma::store_matrix_sync(Ps + (wm*16)*AT_LDS + wn*32 + ni*16, sacc[ni],
                                    AT_LDS, wmma::mem_row_major);
        __syncthreads();

        int ev4[4];
#pragma unroll
        for (int j = 0; j < 4; ++j) ev4[j] = evs[tx*4 + j];
#pragma unroll
        for (int i = 0; i < 4; ++i) {
            int n = nq0 + ty*4 + i;
            float rsum = 0.f;
#pragma unroll
            for (int j = 0; j < 4; ++j) {
                int m = m0 + tx*4 + j;
                float s = Ps[(ty*4+i)*AT_LDS + tx*4 + j];
                bool keep = (m <= n) && (n < ev4[j]);
                float pv = keep ? __expf(s * 0.125f) : 0.f;
                __nv_bfloat16 ph = __float2bfloat16(pv);
                Ph[(ty*4+i)*AT_LDB + tx*4 + j] = ph;
                Pm[(ty*4+i)*AT_LDB + tx*4 + j] = __float2bfloat16(pv - __bfloat162float(ph));
                rsum += pv;
            }
#pragma unroll
            for (int off = 8; off; off >>= 1) rsum += __shfl_xor_sync(0xffffffffu, rsum, off);
            lrow[i] += rsum;
        }
        __syncthreads();

#pragma unroll
        for (int ks = 0; ks < 4; ++ks) {
            wmma::fragment<wmma::matrix_a, 16, 16, 16, __nv_bfloat16, wmma::row_major> pah, pam;
            wmma::load_matrix_sync(pah, Ph + (wm*16)*AT_LDB + ks*16, AT_LDB);
            wmma::load_matrix_sync(pam, Pm + (wm*16)*AT_LDB + ks*16, AT_LDB);
#pragma unroll
            for (int ni = 0; ni < 2; ++ni) {
                wmma::fragment<wmma::matrix_b, 16, 16, 16, __nv_bfloat16, wmma::row_major> vbh, vbm;
                wmma::load_matrix_sync(vbh, Vh + (ks*16)*AT_LDB + wn*32 + ni*16, AT_LDB);
                wmma::load_matrix_sync(vbm, Vm + (ks*16)*AT_LDB + wn*32 + ni*16, AT_LDB);
                wmma::mma_sync(oacc[ni], pah, vbh, oacc[ni]);
                wmma::mma_sync(oacc[ni], pah, vbm, oacc[ni]);
                wmma::mma_sync(oacc[ni], pam, vbh, oacc[ni]);
            }
        }
    }

    __syncthreads();
#pragma unroll
    for (int ni = 0; ni < 2; ++ni)
        wmma::store_matrix_sync(Ps + (wm*16)*AT_LDS + wn*32 + ni*16, oacc[ni],
                                AT_LDS, wmma::mem_row_major);
    __syncthreads();
#pragma unroll
    for (int i = 0; i < 4; ++i) {
        float rl = 1.0f / lrow[i];
        int n = nq0 + ty*4 + i;
        const float* pr = Ps + (ty*4+i)*AT_LDS + tx*4;
        float4 w = make_float4(pr[0]*rl, pr[1]*rl, pr[2]*rl, pr[3]*rl);
        *(float4*)(AO + ((size_t)b*NN + n)*DD + h*DH + tx*4) = w;
    }
}

extern "C" void kernel_launch(void* const* d_in, const int* in_sizes, int n_in,
                              void* d_out, int out_size)
{
    (void)in_sizes; (void)n_in; (void)out_size;
    const float* X  = (const float*)d_in[0];
    const float* Wq = (const float*)d_in[1];
    const float* Wk = (const float*)d_in[2];
    const float* Wv = (const float*)d_in[3];
    const float* Wo = (const float*)d_in[4];
    const float* gq = (const float*)d_in[5];
    const float* bq = (const float*)d_in[6];
    const float* gk = (const float*)d_in[7];
    const float* bk = (const float*)d_in[8];
    float* out = (float*)d_out;

    float *Yq, *Yk, *Qp, *Kp, *Vp, *S0, *Fi, *AO; int* ev;
    cudaGetSymbolAddress((void**)&Yq, g_Yq);
    cudaGetSymbolAddress((void**)&Yk, g_Yk);
    cudaGetSymbolAddress((void**)&Qp, g_Q);
    cudaGetSymbolAddress((void**)&Kp, g_K);
    cudaGetSymbolAddress((void**)&Vp, g_V);
    cudaGetSymbolAddress((void**)&S0, g_S0);
    cudaGetSymbolAddress((void**)&Fi, g_Fi);
    cudaGetSymbolAddress((void**)&ev, g_ev);
    cudaGetSymbolAddress((void**)&AO, g_AO);
    __half *hXa,*hXb,*hWqa,*hWqb,*hWka,*hWkb,*hWva,*hWvb,*hWoa,*hWob,*hAa,*hAb;
    cudaGetSymbolAddress((void**)&hXa, g_hXa);   cudaGetSymbolAddress((void**)&hXb, g_hXb);
    cudaGetSymbolAddress((void**)&hWqa, g_hWqa); cudaGetSymbolAddress((void**)&hWqb, g_hWqb);
    cudaGetSymbolAddress((void**)&hWka, g_hWka); cudaGetSymbolAddress((void**)&hWkb, g_hWkb);
    cudaGetSymbolAddress((void**)&hWva, g_hWva); cudaGetSymbolAddress((void**)&hWvb, g_hWvb);
    cudaGetSymbolAddress((void**)&hWoa, g_hWoa); cudaGetSymbolAddress((void**)&hWob, g_hWob);
    cudaGetSymbolAddress((void**)&hAa, g_hAa);   cudaGetSymbolAddress((void**)&hAb, g_hAb);

    cudaFuncSetAttribute(attn_wmma_kernel, cudaFuncAttributeMaxDynamicSharedMemorySize, ATT2_SMEM);
    cudaFuncSetAttribute(gemm_h2_kernel, cudaFuncAttributeMaxDynamicSharedMemorySize, GH_SMEM);

    dim3 wgrid(32, 32);
    dim3 ggrid(DD/64, RR/128);

    conv2h_kernel<<<RR*DD/256, 256>>>(X, hXa, hXb);
    convW2h_kernel<<<wgrid, dim3(32,8)>>>(Wq, hWqa, hWqb);
    convW2h_kernel<<<wgrid, dim3(32,8)>>>(Wk, hWka, hWkb);
    convW2h_kernel<<<wgrid, dim3(32,8)>>>(Wv, hWva, hWvb);
    convW2h_kernel<<<wgrid, dim3(32,8)>>>(Wo, hWoa, hWob);
    gemm_h2_kernel<<<ggrid, 256, GH_SMEM>>>(hXa, hXb, hWqa, hWqb, Yq, 0);
    gemm_h2_kernel<<<ggrid, 256, GH_SMEM>>>(hXa, hXb, hWka, hWkb, Yk, 0);
    gemm_h2_kernel<<<ggrid, 256, GH_SMEM>>>(hXa, hXb, hWva, hWvb, Vp, 1);
    ln_scatter_kernel<<<RR, 256>>>(Yq, gq, bq, Qp);
    ln_scatter_kernel<<<RR, 256>>>(Yk, gk, bk, Kp);
    s0_kernel<<<dim3(MM/64, NN/64, BB), 256>>>(Qp, Kp, S0);
    finit_kernel<<<dim3(MM/64, BB), 256>>>(S0, Fi);
    scan_kernel<<<BB, 1024>>>(S0, Fi, ev);
    attn_wmma_kernel<<<dim3(NN/64, HH, BB), 256, ATT2_SMEM>>>(Qp, Kp, Vp, ev, AO);
    conv2h_kernel<<<RR*DD/256, 256>>>(AO, hAa, hAb);
    gemm_h2_kernel<<<ggrid, 256, GH_SMEM>>>(hAa, hAb, hWoa, hWob, out, 0);
}

// round 7
// speedup vs baseline: 1.3475x; 1.0140x over previous
#include <cuda_runtime.h>
#include <cuda_bf16.h>
#include <cuda_fp16.h>
#include <mma.h>
#include <cstdint>
#include <cstddef>

using namespace nvcuda;

#define BB 2
#define NN 2048
#define DD 1024
#define HH 16
#define DH 64
#define RR (BB*NN)
#define MM 2048
#define BIGV (1<<30)

// ---------------- scratch ----------------
__device__ float g_Yq[(size_t)RR*DD];
__device__ float g_Yk[(size_t)RR*DD];
__device__ float g_Q[(size_t)BB*HH*NN*DH];
__device__ float g_K[(size_t)BB*HH*NN*DH];
__device__ float g_V[(size_t)BB*HH*NN*DH];
__device__ float g_S0[(size_t)BB*NN*MM];
__device__ float g_Fi[BB*MM];
__device__ int   g_ev[BB*MM];
__device__ float g_AO[(size_t)RR*DD];
// fp16 2-split GEMM operands
__device__ __half g_hXa[(size_t)RR*DD], g_hXb[(size_t)RR*DD];
__device__ __half g_hWqa[(size_t)DD*DD], g_hWqb[(size_t)DD*DD];
__device__ __half g_hWka[(size_t)DD*DD], g_hWkb[(size_t)DD*DD];
__device__ __half g_hWva[(size_t)DD*DD], g_hWvb[(size_t)DD*DD];
__device__ __half g_hWoa[(size_t)DD*DD], g_hWob[(size_t)DD*DD];
__device__ __half g_hAa[(size_t)RR*DD], g_hAb[(size_t)RR*DD];
// bf16 split Q/K/V for attention (precomputed once)
__device__ __nv_bfloat16 g_Qh[(size_t)BB*HH*NN*DH], g_Qm[(size_t)BB*HH*NN*DH];
__device__ __nv_bfloat16 g_Kh[(size_t)BB*HH*NN*DH], g_Km[(size_t)BB*HH*NN*DH];
__device__ __nv_bfloat16 g_Vh[(size_t)BB*HH*NN*DH], g_Vm[(size_t)BB*HH*NN*DH];

// ---------------- conversions (fp16 2-split) ----------------
__global__ void __launch_bounds__(256) conv2h_kernel(
    const float* __restrict__ X, __half* __restrict__ H, __half* __restrict__ M)
{
    int i = blockIdx.x * 256 + threadIdx.x;
    float v = X[i];
    __half h = __float2half_rn(v);
    M[i] = __float2half_rn(v - __half2float(h));
    H[i] = h;
}

__global__ void __launch_bounds__(256) convW2h_kernel(
    const float* __restrict__ W, __half* __restrict__ TH, __half* __restrict__ TM)
{
    __shared__ float tile[32][33];
    int n0 = blockIdx.x * 32, k0 = blockIdx.y * 32;
    int tx = threadIdx.x, ty = threadIdx.y;   // 32 x 8
#pragma unroll
    for (int i = 0; i < 32; i += 8)
        tile[ty + i][tx] = W[(size_t)(k0 + ty + i) * DD + n0 + tx];
    __syncthreads();
#pragma unroll
    for (int i = 0; i < 32; i += 8) {
        float v = tile[tx][ty + i];
        __half h = __float2half_rn(v);
        size_t o = (size_t)(n0 + ty + i) * DD + k0 + tx;
        TH[o] = h;
        TM[o] = __float2half_rn(v - __half2float(h));
    }
}

// elementwise fp32 -> bf16 split (for V)
__global__ void __launch_bounds__(256) conv2bf_kernel(
    const float* __restrict__ X, __nv_bfloat16* __restrict__ H, __nv_bfloat16* __restrict__ M)
{
    int i = blockIdx.x * 256 + threadIdx.x;
    float v = X[i];
    __nv_bfloat16 h = __float2bfloat16(v);
    M[i] = __float2bfloat16(v - __bfloat162float(h));
    H[i] = h;
}

// ---------------- fp16 2-split WMMA GEMM, double-buffered ----------------
#define HPARTA (128*48)
#define HPARTB (64*48)
#define HBUF   (2*HPARTA + 2*HPARTB)
#define GH_SMEM (2*HBUF*2)

__global__ void __launch_bounds__(256) gemm_h2_kernel(
    const __half* __restrict__ A0, const __half* __restrict__ A1,
    const __half* __restrict__ B0, const __half* __restrict__ B1,
    float* __restrict__ C, int scatter)
{
    extern __shared__ __half smh[];
    int tid = threadIdx.x, wid = tid >> 5;
    int wm = wid & 3, wn = wid >> 2;
    int row0 = blockIdx.y * 128, col0 = blockIdx.x * 64;

    const __half* ap[2] = { A0 + (size_t)row0 * DD, A1 + (size_t)row0 * DD };
    const __half* bp[2] = { B0 + (size_t)col0 * DD, B1 + (size_t)col0 * DD };

    int ar0 = (tid * 2) >> 2,     ac0 = ((tid * 2) & 3) * 8;
    int ar1 = (tid * 2 + 1) >> 2, ac1 = ((tid * 2 + 1) & 3) * 8;
    int br  = tid >> 2,           bc  = (tid & 3) * 8;

    wmma::fragment<wmma::accumulator, 16, 16, 16, float> acc[2][2];
#pragma unroll
    for (int i = 0; i < 2; ++i)
#pragma unroll
        for (int j = 0; j < 2; ++j) wmma::fill_fragment(acc[i][j], 0.0f);

    uint4 ra[2][2], rb[2];

#define LOADG(KB) do { \
    ra[0][0] = *(const uint4*)(ap[0] + (size_t)ar0*DD + (KB) + ac0); \
    ra[0][1] = *(const uint4*)(ap[0] + (size_t)ar1*DD + (KB) + ac1); \
    rb[0]    = *(const uint4*)(bp[0] + (size_t)br *DD + (KB) + bc ); \
    ra[1][0] = *(const uint4*)(ap[1] + (size_t)ar0*DD + (KB) + ac0); \
    ra[1][1] = *(const uint4*)(ap[1] + (size_t)ar1*DD + (KB) + ac1); \
    rb[1]    = *(const uint4*)(bp[1] + (size_t)br *DD + (KB) + bc ); \
} while (0)

#define STORES(BUF) do { \
    __half* _b = smh + (BUF)*HBUF; \
    *(uint4*)(_b + 0*HPARTA + ar0*48 + ac0) = ra[0][0]; \
    *(uint4*)(_b + 0*HPARTA + ar1*48 + ac1) = ra[0][1]; \
    *(uint4*)(_b + 1*HPARTA + ar0*48 + ac0) = ra[1][0]; \
    *(uint4*)(_b + 1*HPARTA + ar1*48 + ac1) = ra[1][1]; \
    *(uint4*)(_b + 2*HPARTA + 0*HPARTB + br*48 + bc) = rb[0]; \
    *(uint4*)(_b + 2*HPARTA + 1*HPARTB + br*48 + bc) = rb[1]; \
} while (0)

    LOADG(0);
    STORES(0);
    __syncthreads();

    for (int kt = 0; kt < 32; ++kt) {
        if (kt + 1 < 32) LOADG((kt + 1) * 32);
        __half* Asb = smh + (kt & 1) * HBUF;
        __half* Bsb = Asb + 2 * HPARTA;
#pragma unroll
        for (int ks = 0; ks < 2; ++ks) {
            wmma::fragment<wmma::matrix_a, 16, 16, 16, __half, wmma::row_major> a0f[2], a1f[2];
            wmma::fragment<wmma::matrix_b, 16, 16, 16, __half, wmma::col_major> b0f[2], b1f[2];
#pragma unroll
            for (int mi = 0; mi < 2; ++mi) {
                wmma::load_matrix_sync(a0f[mi], Asb + 0*HPARTA + (wm*32 + mi*16)*48 + ks*16, 48);
                wmma::load_matrix_sync(a1f[mi], Asb + 1*HPARTA + (wm*32 + mi*16)*48 + ks*16, 48);
            }
#pragma unroll
            for (int ni = 0; ni < 2; ++ni) {
                wmma::load_matrix_sync(b0f[ni], Bsb + 0*HPARTB + (wn*32 + ni*16)*48 + ks*16, 48);
                wmma::load_matrix_sync(b1f[ni], Bsb + 1*HPARTB + (wn*32 + ni*16)*48 + ks*16, 48);
            }
#pragma unroll
            for (int mi = 0; mi < 2; ++mi)
#pragma unroll
                for (int ni = 0; ni < 2; ++ni) {
                    wmma::mma_sync(acc[mi][ni], a0f[mi], b0f[ni], acc[mi][ni]);
                    wmma::mma_sync(acc[mi][ni], a0f[mi], b1f[ni], acc[mi][ni]);
                    wmma::mma_sync(acc[mi][ni], a1f[mi], b0f[ni], acc[mi][ni]);
                }
        }
        __syncthreads();
        if (kt + 1 < 32) { STORES((kt + 1) & 1); __syncthreads(); }
    }
#undef LOADG
#undef STORES

#pragma unroll
    for (int mi = 0; mi < 2; ++mi)
#pragma unroll
        for (int ni = 0; ni < 2; ++ni) {
            int r = row0 + wm*32 + mi*16;
            int c = col0 + wn*32 + ni*16;
            if (!scatter) {
                wmma::store_matrix_sync(C + (size_t)r*DD + c, acc[mi][ni], DD, wmma::mem_row_major);
            } else {
                int b = r >> 11, nrow = r & (NN - 1);
                int h = c >> 6,  dh = c & (DH - 1);
                wmma::store_matrix_sync(C + (((size_t)b*HH + h)*NN + nrow)*DH + dh,
                                        acc[mi][ni], DH, wmma::mem_row_major);
            }
        }
}

// ---------------- LayerNorm + head scatter (fp32 + bf16 split outputs) ----------------
__global__ void __launch_bounds__(256) ln_scatter_kernel(
    const float* __restrict__ Y, const float* __restrict__ gam,
    const float* __restrict__ bet, float* __restrict__ O,
    __nv_bfloat16* __restrict__ Oh, __nv_bfloat16* __restrict__ Om)
{
    int row = blockIdx.x, t = threadIdx.x;
    const float* y = Y + (size_t)row * DD;
    float x0 = y[t], x1 = y[t+256], x2 = y[t+512], x3 = y[t+768];
    float s = x0+x1+x2+x3;
    float q = x0*x0 + x1*x1 + x2*x2 + x3*x3;
#pragma unroll
    for (int off = 16; off; off >>= 1) {
        s += __shfl_xor_sync(0xffffffffu, s, off);
        q += __shfl_xor_sync(0xffffffffu, q, off);
    }
    __shared__ float ss[8], sq[8];
    __shared__ float smu, srstd;
    if ((t & 31) == 0) { ss[t>>5] = s; sq[t>>5] = q; }
    __syncthreads();
    if (t == 0) {
        float S = 0.f, Q = 0.f;
#pragma unroll
        for (int i = 0; i < 8; ++i) { S += ss[i]; Q += sq[i]; }
        float mu = S * (1.0f/DD);
        float var = Q * (1.0f/DD) - mu*mu;
        smu = mu; srstd = rsqrtf(var + 1e-5f);
    }
    __syncthreads();
    float mu = smu, rs = srstd;
    int b = row >> 11, n = row & (NN-1);
    float xs[4] = {x0, x1, x2, x3};
#pragma unroll
    for (int i = 0; i < 4; ++i) {
        int d = t + i*256;
        float v = (xs[i] - mu) * rs * gam[d] + bet[d];
        size_t o = (((size_t)b*HH + (d>>6))*NN + n)*DH + (d & (DH-1));
        O[o] = v;
        __nv_bfloat16 h = __float2bfloat16(v);
        Oh[o] = h;
        Om[o] = __float2bfloat16(v - __bfloat162float(h));
    }
}

// ---------------- S0 (fp32 selection path, unchanged) ----------------
__global__ void __launch_bounds__(256) s0_kernel(
    const float* __restrict__ Qv, const float* __restrict__ Kv, float* __restrict__ S0)
{
    int b  = blockIdx.z;
    int j0 = blockIdx.y << 6, m0 = blockIdx.x << 6;
    int tid = threadIdx.x;
    size_t outbase = ((size_t)b*NN + j0)*MM + m0;
    if (m0 >= j0 + 64) {
        for (int idx = tid; idx < 4096; idx += 256) {
            int jj = idx >> 6, mm = idx & 63;
            S0[outbase + (size_t)jj*MM + mm] = 0.f;
        }
        return;
    }
    __shared__ float Qs[64][68];
    __shared__ float Kts[64][64];
    const float* Qb = Qv + (((size_t)b*HH + 0)*NN + j0)*DH;
    const float* Kb = Kv + (((size_t)b*HH + 0)*NN + m0)*DH;
    int r = tid >> 2, c0 = (tid & 3) << 4;
#pragma unroll
    for (int u = 0; u < 4; ++u) {
        float4 v = *(const float4*)(Qb + (size_t)r*DH + c0 + u*4);
        Qs[r][c0+u*4+0] = v.x; Qs[r][c0+u*4+1] = v.y; Qs[r][c0+u*4+2] = v.z; Qs[r][c0+u*4+3] = v.w;
        float4 w = *(const float4*)(Kb + (size_t)r*DH + c0 + u*4);
        Kts[c0+u*4+0][r] = w.x; Kts[c0+u*4+1][r] = w.y; Kts[c0+u*4+2][r] = w.z; Kts[c0+u*4+3][r] = w.w;
    }
    __syncthreads();
    int tx = tid & 15, ty = tid >> 4;
    float acc[4][4] = {};
#pragma unroll 8
    for (int k = 0; k < 64; ++k) {
        float a0 = Qs[ty*4+0][k], a1 = Qs[ty*4+1][k];
        float a2 = Qs[ty*4+2][k], a3 = Qs[ty*4+3][k];
        float4 b4 = *(const float4*)&Kts[k][tx*4];
        acc[0][0] += a0*b4.x; acc[0][1] += a0*b4.y; acc[0][2] += a0*b4.z; acc[0][3] += a0*b4.w;
        acc[1][0] += a1*b4.x; acc[1][1] += a1*b4.y; acc[1][2] += a1*b4.z; acc[1][3] += a1*b4.w;
        acc[2][0] += a2*b4.x; acc[2][1] += a2*b4.y; acc[2][2] += a2*b4.z; acc[2][3] += a2*b4.w;
        acc[3][0] += a3*b4.x; acc[3][1] += a3*b4.y; acc[3][2] += a3*b4.z; acc[3][3] += a3*b4.w;
    }
#pragma unroll
    for (int i = 0; i < 4; ++i) {
        int j = j0 + ty*4 + i;
        int mb = m0 + tx*4;
        float4 w;
        w.x = ((mb+0) == 0 || (mb+0) >= j) ? 0.f : fmaxf(acc[i][0]*0.125f, 0.f);
        w.y = ((mb+1) == 0 || (mb+1) >= j) ? 0.f : fmaxf(acc[i][1]*0.125f, 0.f);
        w.z = ((mb+2) == 0 || (mb+2) >= j) ? 0.f : fmaxf(acc[i][2]*0.125f, 0.f);
        w.w = ((mb+3) == 0 || (mb+3) >= j) ? 0.f : fmaxf(acc[i][3]*0.125f, 0.f);
        *(float4*)(S0 + ((size_t)b*NN + j)*MM + mb) = w;
    }
}

// ---------------- Finit ----------------
__global__ void __launch_bounds__(256) finit_kernel(
    const float* __restrict__ S0, float* __restrict__ Fi)
{
    int b = blockIdx.y;
    int col = (blockIdx.x << 6) + (threadIdx.x & 63);
    int part = threadIdx.x >> 6;
    const float* base = S0 + ((size_t)b*NN + part*256)*MM + col;
    float s = 0.f;
#pragma unroll 4
    for (int r = 0; r < 256; ++r) s += base[(size_t)r*MM];
    __shared__ float ps[256];
    ps[threadIdx.x] = s;
    __syncthreads();
    if (threadIdx.x < 64) {
        Fi[b*MM + (blockIdx.x << 6) + threadIdx.x] =
            ps[threadIdx.x] + ps[threadIdx.x+64] + ps[threadIdx.x+128] + ps[threadIdx.x+192];
    }
}

// ---------------- serial eviction scan (register-resident, 1 sync/step) ----------------
__global__ void __launch_bounds__(1024) scan_kernel(
    const float* __restrict__ S0, const float* __restrict__ Fi, int* __restrict__ evict)
{
    __shared__ float wv[2][32];
    __shared__ int wp[2][32];
    int b = blockIdx.x, t = threadIdx.x;
    int lane = t & 31, w = t >> 5;
    float f0 = Fi[b*MM + t];
    float f1 = Fi[b*MM + 1024 + t];
    bool alive0 = true, alive1 = true;
    evict[b*MM + t] = BIGV;
    evict[b*MM + 1024 + t] = BIGV;
    const float* Sb = S0 + (size_t)b*NN*MM;
    float r0 = 0.f, r1 = 0.f;
    __syncthreads();

    for (int i = 1024; i < 2048; ++i) {
        int pb = i & 1;
        f0 += r0; f1 += r1;
        const float* nrow = Sb + (size_t)i*MM;
        r0 = nrow[t]; r1 = nrow[t + 1024];

        float v0 = alive0 ? f0 : -1e38f;
        float v1 = (alive1 && (t < i - 1024)) ? f1 : -1e38f;
        float v; int p;
        if (v1 > v0) { v = v1; p = 1024 + t; } else { v = v0; p = t; }
#pragma unroll
        for (int off = 16; off; off >>= 1) {
            float ov = __shfl_xor_sync(0xffffffffu, v, off);
            int   op = __shfl_xor_sync(0xffffffffu, p, off);
            if (ov > v || (ov == v && op < p)) { v = ov; p = op; }
        }
        if (lane == 0) { wv[pb][w] = v; wp[pb][w] = p; }
        __syncthreads();
        v = wv[pb][lane]; p = wp[pb][lane];
#pragma unroll
        for (int off = 16; off; off >>= 1) {
            float ov = __shfl_xor_sync(0xffffffffu, v, off);
            int   op = __shfl_xor_sync(0xffffffffu, p, off);
            if (ov > v || (ov == v && op < p)) { v = ov; p = op; }
        }
        if (p == t)             { alive0 = false; evict[b*MM + t] = i; }
        else if (p == 1024 + t) { alive1 = false; evict[b*MM + 1024 + t] = i; }
        // no trailing sync: next iteration writes the other parity buffer
    }
}

// ---------------- WMMA flash attention (precomputed bf16 splits) ----------------
#define AT_LDB 72
#define AT_LDS 68
#define ATT2_SMEM (8*64*AT_LDB*2 + 64*AT_LDS*4 + 64*4)

__global__ void __launch_bounds__(256) attn_wmma_kernel(
    const __nv_bfloat16* __restrict__ Qhg, const __nv_bfloat16* __restrict__ Qmg,
    const __nv_bfloat16* __restrict__ Khg, const __nv_bfloat16* __restrict__ Kmg,
    const __nv_bfloat16* __restrict__ Vhg, const __nv_bfloat16* __restrict__ Vmg,
    const int* __restrict__ ev_g, float* __restrict__ AO)
{
    extern __shared__ char smc[];
    __nv_bfloat16* Qh = (__nv_bfloat16*)smc;
    __nv_bfloat16* Qm = Qh + 64*AT_LDB;
    __nv_bfloat16* Kh = Qm + 64*AT_LDB;
    __nv_bfloat16* Km = Kh + 64*AT_LDB;
    __nv_bfloat16* Vh = Km + 64*AT_LDB;
    __nv_bfloat16* Vm = Vh + 64*AT_LDB;
    __nv_bfloat16* Ph = Vm + 64*AT_LDB;
    __nv_bfloat16* Pm = Ph + 64*AT_LDB;
    float* Ps = (float*)(Pm + 64*AT_LDB);
    int*   evs = (int*)(Ps + 64*AT_LDS);

    int bq = (int)gridDim.x - 1 - (int)blockIdx.x;
    int h = blockIdx.y, b = blockIdx.z;
    int nq0 = bq << 6;
    int tid = threadIdx.x;
    int wid = tid >> 5;
    int tx = tid & 15, ty = tid >> 4;
    int wm = wid & 3, wn = wid >> 2;

    size_t head_off = ((size_t)b*HH + h)*NN;
    int lr = tid >> 2, lc = (tid & 3) * 16;   // 4 threads per 64-elem row, 2 uint4 each

    {
        const __nv_bfloat16* qh = Qhg + (head_off + nq0)*DH;
        const __nv_bfloat16* qm = Qmg + (head_off + nq0)*DH;
        *(uint4*)(Qh + lr*AT_LDB + lc)     = *(const uint4*)(qh + (size_t)lr*DH + lc);
        *(uint4*)(Qh + lr*AT_LDB + lc + 8) = *(const uint4*)(qh + (size_t)lr*DH + lc + 8);
        *(uint4*)(Qm + lr*AT_LDB + lc)     = *(const uint4*)(qm + (size_t)lr*DH + lc);
        *(uint4*)(Qm + lr*AT_LDB + lc + 8) = *(const uint4*)(qm + (size_t)lr*DH + lc + 8);
    }

    wmma::fragment<wmma::accumulator, 16, 16, 16, float> oacc[2];
#pragma unroll
    for (int ni = 0; ni < 2; ++ni) wmma::fill_fragment(oacc[ni], 0.0f);
    float lrow[4] = {0.f, 0.f, 0.f, 0.f};

    for (int kt = 0; kt <= bq; ++kt) {
        int m0 = kt << 6;
        __syncthreads();
        {
            const __nv_bfloat16* kh = Khg + (head_off + m0)*DH;
            const __nv_bfloat16* km = Kmg + (head_off + m0)*DH;
            const __nv_bfloat16* vh = Vhg + (head_off + m0)*DH;
            const __nv_bfloat16* vm = Vmg + (head_off + m0)*DH;
            *(uint4*)(Kh + lr*AT_LDB + lc)     = *(const uint4*)(kh + (size_t)lr*DH + lc);
            *(uint4*)(Kh + lr*AT_LDB + lc + 8) = *(const uint4*)(kh + (size_t)lr*DH + lc + 8);
            *(uint4*)(Km + lr*AT_LDB + lc)     = *(const uint4*)(km + (size_t)lr*DH + lc);
            *(uint4*)(Km + lr*AT_LDB + lc + 8) = *(const uint4*)(km + (size_t)lr*DH + lc + 8);
            *(uint4*)(Vh + lr*AT_LDB + lc)     = *(const uint4*)(vh + (size_t)lr*DH + lc);
            *(uint4*)(Vh + lr*AT_LDB + lc + 8) = *(const uint4*)(vh + (size_t)lr*DH + lc + 8);
            *(uint4*)(Vm + lr*AT_LDB + lc)     = *(const uint4*)(vm + (size_t)lr*DH + lc);
            *(uint4*)(Vm + lr*AT_LDB + lc + 8) = *(const uint4*)(vm + (size_t)lr*DH + lc + 8);
            if (tid < 64) evs[tid] = ev_g[b*MM + m0 + tid];
        }
        __syncthreads();

        wmma::fragment<wmma::accumulator, 16, 16, 16, float> sacc[2];
#pragma unroll
        for (int ni = 0; ni < 2; ++ni) wmma::fill_fragment(sacc[ni], 0.0f);
#pragma unroll
        for (int ks = 0; ks < 4; ++ks) {
            wmma::fragment<wmma::matrix_a, 16, 16, 16, __nv_bfloat16, wmma::row_major> ah, am;
            wmma::load_matrix_sync(ah, Qh + (wm*16)*AT_LDB + ks*16, AT_LDB);
            wmma::load_matrix_sync(am, Qm + (wm*16)*AT_LDB + ks*16, AT_LDB);
#pragma unroll
            for (int ni = 0; ni < 2; ++ni) {
                wmma::fragment<wmma::matrix_b, 16, 16, 16, __nv_bfloat16, wmma::col_major> bh, bm;
                wmma::load_matrix_sync(bh, Kh + (wn*32 + ni*16)*AT_LDB + ks*16, AT_LDB);
                wmma::load_matrix_sync(bm, Km + (wn*32 + ni*16)*AT_LDB + ks*16, AT_LDB);
                wmma::mma_sync(sacc[ni], ah, bh, sacc[ni]);
                wmma::mma_sync(sacc[ni], am, bh, sacc[ni]);
                wmma::mma_sync(sacc[ni], ah, bm, sacc[ni]);
            }
        }
#pragma unroll
        for (int ni = 0; ni < 2; ++ni)
            wmma::store_matrix_sync(Ps + (wm*16)*AT_LDS + wn*32 + ni*16, sacc[ni],
                                    AT_LDS, wmma::mem_row_major);
        __syncthreads();

        int ev4[4];
#pragma unroll
        for (int j = 0; j < 4; ++j) ev4[j] = evs[tx*4 + j];
#pragma unroll
        for (int i = 0; i < 4; ++i) {
            int n = nq0 + ty*4 + i;
            float rsum = 0.f;
#pragma unroll
            for (int j = 0; j < 4; ++j) {
                int m = m0 + tx*4 + j;
                float s = Ps[(ty*4+i)*AT_LDS + tx*4 + j];
                bool keep = (m <= n) && (n < ev4[j]);
                float pv = keep ? __expf(s * 0.125f) : 0.f;
                __nv_bfloat16 ph = __float2bfloat16(pv);
                Ph[(ty*4+i)*AT_LDB + tx*4 + j] = ph;
                Pm[(ty*4+i)*AT_LDB + tx*4 + j] = __float2bfloat16(pv - __bfloat162float(ph));
                rsum += pv;
            }
#pragma unroll
            for (int off = 8; off; off >>= 1) rsum += __shfl_xor_sync(0xffffffffu, rsum, off);
            lrow[i] += rsum;
        }
        __syncthreads();

#pragma unroll
        for (int ks = 0; ks < 4; ++ks) {
            wmma::fragment<wmma::matrix_a, 16, 16, 16, __nv_bfloat16, wmma::row_major> pah, pam;
            wmma::load_matrix_sync(pah, Ph + (wm*16)*AT_LDB + ks*16, AT_LDB);
            wmma::load_matrix_sync(pam, Pm + (wm*16)*AT_LDB + ks*16, AT_LDB);
#pragma unroll
            for (int ni = 0; ni < 2; ++ni) {
                wmma::fragment<wmma::matrix_b, 16, 16, 16, __nv_bfloat16, wmma::row_major> vbh, vbm;
                wmma::load_matrix_sync(vbh, Vh + (ks*16)*AT_LDB + wn*32 + ni*16, AT_LDB);
                wmma::load_matrix_sync(vbm, Vm + (ks*16)*AT_LDB + wn*32 + ni*16, AT_LDB);
                wmma::mma_sync(oacc[ni], pah, vbh, oacc[ni]);
                wmma::mma_sync(oacc[ni], pah, vbm, oacc[ni]);
                wmma::mma_sync(oacc[ni], pam, vbh, oacc[ni]);
            }
        }
    }

    __syncthreads();
#pragma unroll
    for (int ni = 0; ni < 2; ++ni)
        wmma::store_matrix_sync(Ps + (wm*16)*AT_LDS + wn*32 + ni*16, oacc[ni],
                                AT_LDS, wmma::mem_row_major);
    __syncthreads();
#pragma unroll
    for (int i = 0; i < 4; ++i) {
        float rl = 1.0f / lrow[i];
        int n = nq0 + ty*4 + i;
        const float* pr = Ps + (ty*4+i)*AT_LDS + tx*4;
        float4 w = make_float4(pr[0]*rl, pr[1]*rl, pr[2]*rl, pr[3]*rl);
        *(float4*)(AO + ((size_t)b*NN + n)*DD + h*DH + tx*4) = w;
    }
}

extern "C" void kernel_launch(void* const* d_in, const int* in_sizes, int n_in,
                              void* d_out, int out_size)
{
    (void)in_sizes; (void)n_in; (void)out_size;
    const float* X  = (const float*)d_in[0];
    const float* Wq = (const float*)d_in[1];
    const float* Wk = (const float*)d_in[2];
    const float* Wv = (const float*)d_in[3];
    const float* Wo = (const float*)d_in[4];
    const float* gq = (const float*)d_in[5];
    const float* bq = (const float*)d_in[6];
    const float* gk = (const float*)d_in[7];
    const float* bk = (const float*)d_in[8];
    float* out = (float*)d_out;

    float *Yq, *Yk, *Qp, *Kp, *Vp, *S0, *Fi, *AO; int* ev;
    cudaGetSymbolAddress((void**)&Yq, g_Yq);
    cudaGetSymbolAddress((void**)&Yk, g_Yk);
    cudaGetSymbolAddress((void**)&Qp, g_Q);
    cudaGetSymbolAddress((void**)&Kp, g_K);
    cudaGetSymbolAddress((void**)&Vp, g_V);
    cudaGetSymbolAddress((void**)&S0, g_S0);
    cudaGetSymbolAddress((void**)&Fi, g_Fi);
    cudaGetSymbolAddress((void**)&ev, g_ev);
    cudaGetSymbolAddress((void**)&AO, g_AO);
    __half *hXa,*hXb,*hWqa,*hWqb,*hWka,*hWkb,*hWva,*hWvb,*hWoa,*hWob,*hAa,*hAb;
    cudaGetSymbolAddress((void**)&hXa, g_hXa);   cudaGetSymbolAddress((void**)&hXb, g_hXb);
    cudaGetSymbolAddress((void**)&hWqa, g_hWqa); cudaGetSymbolAddress((void**)&hWqb, g_hWqb);
    cudaGetSymbolAddress((void**)&hWka, g_hWka); cudaGetSymbolAddress((void**)&hWkb, g_hWkb);
    cudaGetSymbolAddress((void**)&hWva, g_hWva); cudaGetSymbolAddress((void**)&hWvb, g_hWvb);
    cudaGetSymbolAddress((void**)&hWoa, g_hWoa); cudaGetSymbolAddress((void**)&hWob, g_hWob);
    cudaGetSymbolAddress((void**)&hAa, g_hAa);   cudaGetSymbolAddress((void**)&hAb, g_hAb);
    __nv_bfloat16 *Qh,*Qm,*Kh,*Km,*Vh,*Vm;
    cudaGetSymbolAddress((void**)&Qh, g_Qh); cudaGetSymbolAddress((void**)&Qm, g_Qm);
    cudaGetSymbolAddress((void**)&Kh, g_Kh); cudaGetSymbolAddress((void**)&Km, g_Km);
    cudaGetSymbolAddress((void**)&Vh, g_Vh); cudaGetSymbolAddress((void**)&Vm, g_Vm);

    cudaFuncSetAttribute(attn_wmma_kernel, cudaFuncAttributeMaxDynamicSharedMemorySize, ATT2_SMEM);
    cudaFuncSetAttribute(gemm_h2_kernel, cudaFuncAttributeMaxDynamicSharedMemorySize, GH_SMEM);

    dim3 wgrid(32, 32);
    dim3 ggrid(DD/64, RR/128);

    conv2h_kernel<<<RR*DD/256, 256>>>(X, hXa, hXb);                    // 0
    convW2h_kernel<<<wgrid, dim3(32,8)>>>(Wq, hWqa, hWqb);             // 1
    convW2h_kernel<<<wgrid, dim3(32,8)>>>(Wk, hWka, hWkb);             // 2
    convW2h_kernel<<<wgrid, dim3(32,8)>>>(Wv, hWva, hWvb);             // 3
    gemm_h2_kernel<<<ggrid, 256, GH_SMEM>>>(hXa, hXb, hWqa, hWqb, Yq, 0);   // 4 (profiled)
    convW2h_kernel<<<wgrid, dim3(32,8)>>>(Wo, hWoa, hWob);
    gemm_h2_kernel<<<ggrid, 256, GH_SMEM>>>(hXa, hXb, hWka, hWkb, Yk, 0);
    gemm_h2_kernel<<<ggrid, 256, GH_SMEM>>>(hXa, hXb, hWva, hWvb, Vp, 1);
    ln_scatter_kernel<<<RR, 256>>>(Yq, gq, bq, Qp, Qh, Qm);
    ln_scatter_kernel<<<RR, 256>>>(Yk, gk, bk, Kp, Kh, Km);
    conv2bf_kernel<<<RR*DD/256, 256>>>(Vp, Vh, Vm);
    s0_kernel<<<dim3(MM/64, NN/64, BB), 256>>>(Qp, Kp, S0);
    finit_kernel<<<dim3(MM/64, BB), 256>>>(S0, Fi);
    scan_kernel<<<BB, 1024>>>(S0, Fi, ev);
    attn_wmma_kernel<<<dim3(NN/64, HH, BB), 256, ATT2_SMEM>>>(Qh, Qm, Kh, Km, Vh, Vm, ev, AO);
    conv2h_kernel<<<RR*DD/256, 256>>>(AO, hAa, hAb);
    gemm_h2_kernel<<<ggrid, 256, GH_SMEM>>>(hAa, hAb, hWoa, hWob, out, 0);
}

// round 8
// speedup vs baseline: 1.3525x; 1.0037x over previous
#include <cuda_runtime.h>
#include <cuda_bf16.h>
#include <cuda_fp16.h>
#include <mma.h>
#include <cstdint>
#include <cstddef>

using namespace nvcuda;

#define BB 2
#define NN 2048
#define DD 1024
#define HH 16
#define DH 64
#define RR (BB*NN)
#define MM 2048
#define BIGV (1<<30)

// ---------------- scratch ----------------
__device__ float g_Yq[(size_t)RR*DD];
__device__ float g_Yk[(size_t)RR*DD];
__device__ float g_Q[(size_t)BB*HH*NN*DH];
__device__ float g_K[(size_t)BB*HH*NN*DH];
__device__ float g_S0[(size_t)BB*NN*MM];
__device__ float g_Fi[BB*MM];
__device__ int   g_ev[BB*MM];
// fp16 2-split GEMM operands
__device__ __half g_hXa[(size_t)RR*DD], g_hXb[(size_t)RR*DD];
__device__ __half g_hWqa[(size_t)DD*DD], g_hWqb[(size_t)DD*DD];
__device__ __half g_hWka[(size_t)DD*DD], g_hWkb[(size_t)DD*DD];
__device__ __half g_hWva[(size_t)DD*DD], g_hWvb[(size_t)DD*DD];
__device__ __half g_hWoa[(size_t)DD*DD], g_hWob[(size_t)DD*DD];
__device__ __half g_hAa[(size_t)RR*DD], g_hAb[(size_t)RR*DD];
// bf16 split Q/K/V for attention
__device__ __nv_bfloat16 g_Qh[(size_t)BB*HH*NN*DH], g_Qm[(size_t)BB*HH*NN*DH];
__device__ __nv_bfloat16 g_Kh[(size_t)BB*HH*NN*DH], g_Km[(size_t)BB*HH*NN*DH];
__device__ __nv_bfloat16 g_Vh[(size_t)BB*HH*NN*DH], g_Vm[(size_t)BB*HH*NN*DH];

// ---------------- conversions ----------------
// vectorized fp32 -> fp16 2-split (4 elems/thread)
__global__ void __launch_bounds__(256) conv2h_kernel(
    const float* __restrict__ X, __half* __restrict__ H, __half* __restrict__ M)
{
    int i = (blockIdx.x * 256 + threadIdx.x) * 4;
    float4 v = *(const float4*)(X + i);
    __half h0 = __float2half_rn(v.x), h1 = __float2half_rn(v.y);
    __half h2 = __float2half_rn(v.z), h3 = __float2half_rn(v.w);
    __half2 ha = __halves2half2(h0, h1), hb = __halves2half2(h2, h3);
    __half2 ma = __halves2half2(__float2half_rn(v.x - __half2float(h0)),
                                __float2half_rn(v.y - __half2float(h1)));
    __half2 mb = __halves2half2(__float2half_rn(v.z - __half2float(h2)),
                                __float2half_rn(v.w - __half2float(h3)));
    *(__half2*)(H + i) = ha; *(__half2*)(H + i + 2) = hb;
    *(__half2*)(M + i) = ma; *(__half2*)(M + i + 2) = mb;
}

__global__ void __launch_bounds__(256) convW2h_kernel(
    const float* __restrict__ W, __half* __restrict__ TH, __half* __restrict__ TM)
{
    __shared__ float tile[32][33];
    int n0 = blockIdx.x * 32, k0 = blockIdx.y * 32;
    int tx = threadIdx.x, ty = threadIdx.y;   // 32 x 8
#pragma unroll
    for (int i = 0; i < 32; i += 8)
        tile[ty + i][tx] = W[(size_t)(k0 + ty + i) * DD + n0 + tx];
    __syncthreads();
#pragma unroll
    for (int i = 0; i < 32; i += 8) {
        float v = tile[tx][ty + i];
        __half h = __float2half_rn(v);
        size_t o = (size_t)(n0 + ty + i) * DD + k0 + tx;
        TH[o] = h;
        TM[o] = __float2half_rn(v - __half2float(h));
    }
}

// ---------------- fp16 2-split WMMA GEMM, double-buffered, 1 sync/iter ----------------
// mode 0: C fp32 row-major.  mode 1: write bf16 split scatter (Vh/Vm), C unused.
#define HPARTA (128*48)
#define HPARTB (64*48)
#define HBUF   (2*HPARTA + 2*HPARTB)
#define GH_SMEM (2*HBUF*2)

__global__ void __launch_bounds__(256) gemm_h2_kernel(
    const __half* __restrict__ A0, const __half* __restrict__ A1,
    const __half* __restrict__ B0, const __half* __restrict__ B1,
    float* __restrict__ C,
    __nv_bfloat16* __restrict__ SH, __nv_bfloat16* __restrict__ SM,
    int mode)
{
    extern __shared__ __half smh[];
    int tid = threadIdx.x, wid = tid >> 5;
    int wm = wid & 3, wn = wid >> 2;
    int row0 = blockIdx.y * 128, col0 = blockIdx.x * 64;

    const __half* ap[2] = { A0 + (size_t)row0 * DD, A1 + (size_t)row0 * DD };
    const __half* bp[2] = { B0 + (size_t)col0 * DD, B1 + (size_t)col0 * DD };

    int ar0 = (tid * 2) >> 2,     ac0 = ((tid * 2) & 3) * 8;
    int ar1 = (tid * 2 + 1) >> 2, ac1 = ((tid * 2 + 1) & 3) * 8;
    int br  = tid >> 2,           bc  = (tid & 3) * 8;

    wmma::fragment<wmma::accumulator, 16, 16, 16, float> acc[2][2];
#pragma unroll
    for (int i = 0; i < 2; ++i)
#pragma unroll
        for (int j = 0; j < 2; ++j) wmma::fill_fragment(acc[i][j], 0.0f);

    uint4 ra[2][2], rb[2];

#define LOADG(KB) do { \
    ra[0][0] = *(const uint4*)(ap[0] + (size_t)ar0*DD + (KB) + ac0); \
    ra[0][1] = *(const uint4*)(ap[0] + (size_t)ar1*DD + (KB) + ac1); \
    rb[0]    = *(const uint4*)(bp[0] + (size_t)br *DD + (KB) + bc ); \
    ra[1][0] = *(const uint4*)(ap[1] + (size_t)ar0*DD + (KB) + ac0); \
    ra[1][1] = *(const uint4*)(ap[1] + (size_t)ar1*DD + (KB) + ac1); \
    rb[1]    = *(const uint4*)(bp[1] + (size_t)br *DD + (KB) + bc ); \
} while (0)

#define STORES(BUF) do { \
    __half* _b = smh + (BUF)*HBUF; \
    *(uint4*)(_b + 0*HPARTA + ar0*48 + ac0) = ra[0][0]; \
    *(uint4*)(_b + 0*HPARTA + ar1*48 + ac1) = ra[0][1]; \
    *(uint4*)(_b + 1*HPARTA + ar0*48 + ac0) = ra[1][0]; \
    *(uint4*)(_b + 1*HPARTA + ar1*48 + ac1) = ra[1][1]; \
    *(uint4*)(_b + 2*HPARTA + 0*HPARTB + br*48 + bc) = rb[0]; \
    *(uint4*)(_b + 2*HPARTA + 1*HPARTB + br*48 + bc) = rb[1]; \
} while (0)

    LOADG(0);
    STORES(0);
    __syncthreads();

    for (int kt = 0; kt < 32; ++kt) {
        if (kt + 1 < 32) LOADG((kt + 1) * 32);
        __half* Asb = smh + (kt & 1) * HBUF;
        __half* Bsb = Asb + 2 * HPARTA;
#pragma unroll
        for (int ks = 0; ks < 2; ++ks) {
            wmma::fragment<wmma::matrix_a, 16, 16, 16, __half, wmma::row_major> a0f[2], a1f[2];
            wmma::fragment<wmma::matrix_b, 16, 16, 16, __half, wmma::col_major> b0f[2], b1f[2];
#pragma unroll
            for (int mi = 0; mi < 2; ++mi) {
                wmma::load_matrix_sync(a0f[mi], Asb + 0*HPARTA + (wm*32 + mi*16)*48 + ks*16, 48);
                wmma::load_matrix_sync(a1f[mi], Asb + 1*HPARTA + (wm*32 + mi*16)*48 + ks*16, 48);
            }
#pragma unroll
            for (int ni = 0; ni < 2; ++ni) {
                wmma::load_matrix_sync(b0f[ni], Bsb + 0*HPARTB + (wn*32 + ni*16)*48 + ks*16, 48);
                wmma::load_matrix_sync(b1f[ni], Bsb + 1*HPARTB + (wn*32 + ni*16)*48 + ks*16, 48);
            }
#pragma unroll
            for (int mi = 0; mi < 2; ++mi)
#pragma unroll
                for (int ni = 0; ni < 2; ++ni) {
                    wmma::mma_sync(acc[mi][ni], a0f[mi], b0f[ni], acc[mi][ni]);
                    wmma::mma_sync(acc[mi][ni], a0f[mi], b1f[ni], acc[mi][ni]);
                    wmma::mma_sync(acc[mi][ni], a1f[mi], b0f[ni], acc[mi][ni]);
                }
        }
        // store NEXT tile into the other buffer (disjoint from the one MMA reads),
        // then single barrier. Prior barrier guarantees no warp is still in kt-1.
        if (kt + 1 < 32) STORES((kt + 1) & 1);
        __syncthreads();
    }
#undef LOADG
#undef STORES

    if (mode == 0) {
#pragma unroll
        for (int mi = 0; mi < 2; ++mi)
#pragma unroll
            for (int ni = 0; ni < 2; ++ni) {
                int r = row0 + wm*32 + mi*16;
                int c = col0 + wn*32 + ni*16;
                wmma::store_matrix_sync(C + (size_t)r*DD + c, acc[mi][ni], DD, wmma::mem_row_major);
            }
    } else {
        // stage fp32 tile in smem, then emit bf16 split with head scatter
        float* stage = (float*)smh;   // 128 x 68
#pragma unroll
        for (int mi = 0; mi < 2; ++mi)
#pragma unroll
            for (int ni = 0; ni < 2; ++ni)
                wmma::store_matrix_sync(stage + (wm*32 + mi*16)*68 + wn*32 + ni*16,
                                        acc[mi][ni], 68, wmma::mem_row_major);
        __syncthreads();
        int hh = col0 >> 6;
#pragma unroll 8
        for (int idx = tid; idx < 128*64; idx += 256) {
            int r = idx >> 6, c = idx & 63;
            float v = stage[r*68 + c];
            int gr = row0 + r;
            int b = gr >> 11, n = gr & (NN - 1);
            size_t o = (((size_t)b*HH + hh)*NN + n)*DH + c;
            __nv_bfloat16 h = __float2bfloat16(v);
            SH[o] = h;
            SM[o] = __float2bfloat16(v - __bfloat162float(h));
        }
    }
}

// ---------------- LayerNorm + head scatter (fp32 + bf16 split outputs) ----------------
__global__ void __launch_bounds__(256) ln_scatter_kernel(
    const float* __restrict__ Y, const float* __restrict__ gam,
    const float* __restrict__ bet, float* __restrict__ O,
    __nv_bfloat16* __restrict__ Oh, __nv_bfloat16* __restrict__ Om)
{
    int row = blockIdx.x, t = threadIdx.x;
    const float* y = Y + (size_t)row * DD;
    float x0 = y[t], x1 = y[t+256], x2 = y[t+512], x3 = y[t+768];
    float s = x0+x1+x2+x3;
    float q = x0*x0 + x1*x1 + x2*x2 + x3*x3;
#pragma unroll
    for (int off = 16; off; off >>= 1) {
        s += __shfl_xor_sync(0xffffffffu, s, off);
        q += __shfl_xor_sync(0xffffffffu, q, off);
    }
    __shared__ float ss[8], sq[8];
    __shared__ float smu, srstd;
    if ((t & 31) == 0) { ss[t>>5] = s; sq[t>>5] = q; }
    __syncthreads();
    if (t == 0) {
        float S = 0.f, Q = 0.f;
#pragma unroll
        for (int i = 0; i < 8; ++i) { S += ss[i]; Q += sq[i]; }
        float mu = S * (1.0f/DD);
        float var = Q * (1.0f/DD) - mu*mu;
        smu = mu; srstd = rsqrtf(var + 1e-5f);
    }
    __syncthreads();
    float mu = smu, rs = srstd;
    int b = row >> 11, n = row & (NN-1);
    float xs[4] = {x0, x1, x2, x3};
#pragma unroll
    for (int i = 0; i < 4; ++i) {
        int d = t + i*256;
        float v = (xs[i] - mu) * rs * gam[d] + bet[d];
        size_t o = (((size_t)b*HH + (d>>6))*NN + n)*DH + (d & (DH-1));
        O[o] = v;
        __nv_bfloat16 h = __float2bfloat16(v);
        Oh[o] = h;
        Om[o] = __float2bfloat16(v - __bfloat162float(h));
    }
}

// ---------------- S0 (fp32 selection path, unchanged) ----------------
__global__ void __launch_bounds__(256) s0_kernel(
    const float* __restrict__ Qv, const float* __restrict__ Kv, float* __restrict__ S0)
{
    int b  = blockIdx.z;
    int j0 = blockIdx.y << 6, m0 = blockIdx.x << 6;
    int tid = threadIdx.x;
    size_t outbase = ((size_t)b*NN + j0)*MM + m0;
    if (m0 >= j0 + 64) {
        for (int idx = tid; idx < 4096; idx += 256) {
            int jj = idx >> 6, mm = idx & 63;
            S0[outbase + (size_t)jj*MM + mm] = 0.f;
        }
        return;
    }
    __shared__ float Qs[64][68];
    __shared__ float Kts[64][64];
    const float* Qb = Qv + (((size_t)b*HH + 0)*NN + j0)*DH;
    const float* Kb = Kv + (((size_t)b*HH + 0)*NN + m0)*DH;
    int r = tid >> 2, c0 = (tid & 3) << 4;
#pragma unroll
    for (int u = 0; u < 4; ++u) {
        float4 v = *(const float4*)(Qb + (size_t)r*DH + c0 + u*4);
        Qs[r][c0+u*4+0] = v.x; Qs[r][c0+u*4+1] = v.y; Qs[r][c0+u*4+2] = v.z; Qs[r][c0+u*4+3] = v.w;
        float4 w = *(const float4*)(Kb + (size_t)r*DH + c0 + u*4);
        Kts[c0+u*4+0][r] = w.x; Kts[c0+u*4+1][r] = w.y; Kts[c0+u*4+2][r] = w.z; Kts[c0+u*4+3][r] = w.w;
    }
    __syncthreads();
    int tx = tid & 15, ty = tid >> 4;
    float acc[4][4] = {};
#pragma unroll 8
    for (int k = 0; k < 64; ++k) {
        float a0 = Qs[ty*4+0][k], a1 = Qs[ty*4+1][k];
        float a2 = Qs[ty*4+2][k], a3 = Qs[ty*4+3][k];
        float4 b4 = *(const float4*)&Kts[k][tx*4];
        acc[0][0] += a0*b4.x; acc[0][1] += a0*b4.y; acc[0][2] += a0*b4.z; acc[0][3] += a0*b4.w;
        acc[1][0] += a1*b4.x; acc[1][1] += a1*b4.y; acc[1][2] += a1*b4.z; acc[1][3] += a1*b4.w;
        acc[2][0] += a2*b4.x; acc[2][1] += a2*b4.y; acc[2][2] += a2*b4.z; acc[2][3] += a2*b4.w;
        acc[3][0] += a3*b4.x; acc[3][1] += a3*b4.y; acc[3][2] += a3*b4.z; acc[3][3] += a3*b4.w;
    }
#pragma unroll
    for (int i = 0; i < 4; ++i) {
        int j = j0 + ty*4 + i;
        int mb = m0 + tx*4;
        float4 w;
        w.x = ((mb+0) == 0 || (mb+0) >= j) ? 0.f : fmaxf(acc[i][0]*0.125f, 0.f);
        w.y = ((mb+1) == 0 || (mb+1) >= j) ? 0.f : fmaxf(acc[i][1]*0.125f, 0.f);
        w.z = ((mb+2) == 0 || (mb+2) >= j) ? 0.f : fmaxf(acc[i][2]*0.125f, 0.f);
        w.w = ((mb+3) == 0 || (mb+3) >= j) ? 0.f : fmaxf(acc[i][3]*0.125f, 0.f);
        *(float4*)(S0 + ((size_t)b*NN + j)*MM + mb) = w;
    }
}

// ---------------- Finit ----------------
__global__ void __launch_bounds__(256) finit_kernel(
    const float* __restrict__ S0, float* __restrict__ Fi)
{
    int b = blockIdx.y;
    int col = (blockIdx.x << 6) + (threadIdx.x & 63);
    int part = threadIdx.x >> 6;
    const float* base = S0 + ((size_t)b*NN + part*256)*MM + col;
    float s = 0.f;
#pragma unroll 4
    for (int r = 0; r < 256; ++r) s += base[(size_t)r*MM];
    __shared__ float ps[256];
    ps[threadIdx.x] = s;
    __syncthreads();
    if (threadIdx.x < 64) {
        Fi[b*MM + (blockIdx.x << 6) + threadIdx.x] =
            ps[threadIdx.x] + ps[threadIdx.x+64] + ps[threadIdx.x+128] + ps[threadIdx.x+192];
    }
}

// ---------------- serial eviction scan (register-resident, depth-2 prefetch, 1 sync) ----------------
__global__ void __launch_bounds__(1024) scan_kernel(
    const float* __restrict__ S0, const float* __restrict__ Fi, int* __restrict__ evict)
{
    __shared__ float wv[2][32];
    __shared__ int wp[2][32];
    int b = blockIdx.x, t = threadIdx.x;
    int lane = t & 31, w = t >> 5;
    float f0 = Fi[b*MM + t];
    float f1 = Fi[b*MM + 1024 + t];
    bool alive0 = true, alive1 = true;
    evict[b*MM + t] = BIGV;
    evict[b*MM + 1024 + t] = BIGV;
    const float* Sb = S0 + (size_t)b*NN*MM;
    // addA = row added this step (row i-1); addB = row for next step (row i)
    float a0 = 0.f, a1 = 0.f;
    float b0 = Sb[(size_t)1024*MM + t], b1 = Sb[(size_t)1024*MM + 1024 + t];
    __syncthreads();

    for (int i = 1024; i < 2048; ++i) {
        int pb = i & 1;
        f0 += a0; f1 += a1;
        a0 = b0; a1 = b1;
        int ld = (i + 1 < 2048) ? i + 1 : 2047;      // row i+1, used at step i+2
        const float* nrow = Sb + (size_t)ld*MM;
        b0 = nrow[t]; b1 = nrow[t + 1024];

        float v0 = alive0 ? f0 : -1e38f;
        float v1 = (alive1 && (t < i - 1024)) ? f1 : -1e38f;
        float v; int p;
        if (v1 > v0) { v = v1; p = 1024 + t; } else { v = v0; p = t; }
#pragma unroll
        for (int off = 16; off; off >>= 1) {
            float ov = __shfl_xor_sync(0xffffffffu, v, off);
            int   op = __shfl_xor_sync(0xffffffffu, p, off);
            if (ov > v || (ov == v && op < p)) { v = ov; p = op; }
        }
        if (lane == 0) { wv[pb][w] = v; wp[pb][w] = p; }
        __syncthreads();
        v = wv[pb][lane]; p = wp[pb][lane];
#pragma unroll
        for (int off = 16; off; off >>= 1) {
            float ov = __shfl_xor_sync(0xffffffffu, v, off);
            int   op = __shfl_xor_sync(0xffffffffu, p, off);
            if (ov > v || (ov == v && op < p)) { v = ov; p = op; }
        }
        if (p == t)             { alive0 = false; evict[b*MM + t] = i; }
        else if (p == 1024 + t) { alive1 = false; evict[b*MM + 1024 + t] = i; }
    }
}

// ---------------- WMMA flash attention (precomputed bf16 splits, fp16-split output) ----------------
#define AT_LDB 72
#define AT_LDS 68
#define ATT2_SMEM (8*64*AT_LDB*2 + 64*AT_LDS*4 + 64*4)

__global__ void __launch_bounds__(256) attn_wmma_kernel(
    const __nv_bfloat16* __restrict__ Qhg, const __nv_bfloat16* __restrict__ Qmg,
    const __nv_bfloat16* __restrict__ Khg, const __nv_bfloat16* __restrict__ Kmg,
    const __nv_bfloat16* __restrict__ Vhg, const __nv_bfloat16* __restrict__ Vmg,
    const int* __restrict__ ev_g,
    __half* __restrict__ Aa, __half* __restrict__ Ab)
{
    extern __shared__ char smc[];
    __nv_bfloat16* Qh = (__nv_bfloat16*)smc;
    __nv_bfloat16* Qm = Qh + 64*AT_LDB;
    __nv_bfloat16* Kh = Qm + 64*AT_LDB;
    __nv_bfloat16* Km = Kh + 64*AT_LDB;
    __nv_bfloat16* Vh = Km + 64*AT_LDB;
    __nv_bfloat16* Vm = Vh + 64*AT_LDB;
    __nv_bfloat16* Ph = Vm + 64*AT_LDB;
    __nv_bfloat16* Pm = Ph + 64*AT_LDB;
    float* Ps = (float*)(Pm + 64*AT_LDB);
    int*   evs = (int*)(Ps + 64*AT_LDS);

    int bq = (int)gridDim.x - 1 - (int)blockIdx.x;
    int h = blockIdx.y, b = blockIdx.z;
    int nq0 = bq << 6;
    int tid = threadIdx.x;
    int wid = tid >> 5;
    int tx = tid & 15, ty = tid >> 4;
    int wm = wid & 3, wn = wid >> 2;

    size_t head_off = ((size_t)b*HH + h)*NN;
    int lr = tid >> 2, lc = (tid & 3) * 16;

    {
        const __nv_bfloat16* qh = Qhg + (head_off + nq0)*DH;
        const __nv_bfloat16* qm = Qmg + (head_off + nq0)*DH;
        *(uint4*)(Qh + lr*AT_LDB + lc)     = *(const uint4*)(qh + (size_t)lr*DH + lc);
        *(uint4*)(Qh + lr*AT_LDB + lc + 8) = *(const uint4*)(qh + (size_t)lr*DH + lc + 8);
        *(uint4*)(Qm + lr*AT_LDB + lc)     = *(const uint4*)(qm + (size_t)lr*DH + lc);
        *(uint4*)(Qm + lr*AT_LDB + lc + 8) = *(const uint4*)(qm + (size_t)lr*DH + lc + 8);
    }

    wmma::fragment<wmma::accumulator, 16, 16, 16, float> oacc[2];
#pragma unroll
    for (int ni = 0; ni < 2; ++ni) wmma::fill_fragment(oacc[ni], 0.0f);
    float lrow[4] = {0.f, 0.f, 0.f, 0.f};

    for (int kt = 0; kt <= bq; ++kt) {
        int m0 = kt << 6;
        __syncthreads();
        {
            const __nv_bfloat16* kh = Khg + (head_off + m0)*DH;
            const __nv_bfloat16* km = Kmg + (head_off + m0)*DH;
            const __nv_bfloat16* vh = Vhg + (head_off + m0)*DH;
            const __nv_bfloat16* vm = Vmg + (head_off + m0)*DH;
            *(uint4*)(Kh + lr*AT_LDB + lc)     = *(const uint4*)(kh + (size_t)lr*DH + lc);
            *(uint4*)(Kh + lr*AT_LDB + lc + 8) = *(const uint4*)(kh + (size_t)lr*DH + lc + 8);
            *(uint4*)(Km + lr*AT_LDB + lc)     = *(const uint4*)(km + (size_t)lr*DH + lc);
            *(uint4*)(Km + lr*AT_LDB + lc + 8) = *(const uint4*)(km + (size_t)lr*DH + lc + 8);
            *(uint4*)(Vh + lr*AT_LDB + lc)     = *(const uint4*)(vh + (size_t)lr*DH + lc);
            *(uint4*)(Vh + lr*AT_LDB + lc + 8) = *(const uint4*)(vh + (size_t)lr*DH + lc + 8);
            *(uint4*)(Vm + lr*AT_LDB + lc)     = *(const uint4*)(vm + (size_t)lr*DH + lc);
            *(uint4*)(Vm + lr*AT_LDB + lc + 8) = *(const uint4*)(vm + (size_t)lr*DH + lc + 8);
            if (tid < 64) evs[tid] = ev_g[b*MM + m0 + tid];
        }
        __syncthreads();

        wmma::fragment<wmma::accumulator, 16, 16, 16, float> sacc[2];
#pragma unroll
        for (int ni = 0; ni < 2; ++ni) wmma::fill_fragment(sacc[ni], 0.0f);
#pragma unroll
        for (int ks = 0; ks < 4; ++ks) {
            wmma::fragment<wmma::matrix_a, 16, 16, 16, __nv_bfloat16, wmma::row_major> ah, am;
            wmma::load_matrix_sync(ah, Qh + (wm*16)*AT_LDB + ks*16, AT_LDB);
            wmma::load_matrix_sync(am, Qm + (wm*16)*AT_LDB + ks*16, AT_LDB);
#pragma unroll
            for (int ni = 0; ni < 2; ++ni) {
                wmma::fragment<wmma::matrix_b, 16, 16, 16, __nv_bfloat16, wmma::col_major> bh, bm;
                wmma::load_matrix_sync(bh, Kh + (wn*32 + ni*16)*AT_LDB + ks*16, AT_LDB);
                wmma::load_matrix_sync(bm, Km + (wn*32 + ni*16)*AT_LDB + ks*16, AT_LDB);
                wmma::mma_sync(sacc[ni], ah, bh, sacc[ni]);
                wmma::mma_sync(sacc[ni], am, bh, sacc[ni]);
                wmma::mma_sync(sacc[ni], ah, bm, sacc[ni]);
            }
        }
#pragma unroll
        for (int ni = 0; ni < 2; ++ni)
            wmma::store_matrix_sync(Ps + (wm*16)*AT_LDS + wn*32 + ni*16, sacc[ni],
                                    AT_LDS, wmma::mem_row_major);
        __syncthreads();

        int ev4[4];
#pragma unroll
        for (int j = 0; j < 4; ++j) ev4[j] = evs[tx*4 + j];
#pragma unroll
        for (int i = 0; i < 4; ++i) {
            int n = nq0 + ty*4 + i;
            float rsum = 0.f;
#pragma unroll
            for (int j = 0; j < 4; ++j) {
                int m = m0 + tx*4 + j;
                float s = Ps[(ty*4+i)*AT_LDS + tx*4 + j];
                bool keep = (m <= n) && (n < ev4[j]);
                float pv = keep ? __expf(s * 0.125f) : 0.f;
                __nv_bfloat16 ph = __float2bfloat16(pv);
                Ph[(ty*4+i)*AT_LDB + tx*4 + j] = ph;
                Pm[(ty*4+i)*AT_LDB + tx*4 + j] = __float2bfloat16(pv - __bfloat162float(ph));
                rsum += pv;
            }
#pragma unroll
            for (int off = 8; off; off >>= 1) rsum += __shfl_xor_sync(0xffffffffu, rsum, off);
            lrow[i] += rsum;
        }
        __syncthreads();

#pragma unroll
        for (int ks = 0; ks < 4; ++ks) {
            wmma::fragment<wmma::matrix_a, 16, 16, 16, __nv_bfloat16, wmma::row_major> pah, pam;
            wmma::load_matrix_sync(pah, Ph + (wm*16)*AT_LDB + ks*16, AT_LDB);
            wmma::load_matrix_sync(pam, Pm + (wm*16)*AT_LDB + ks*16, AT_LDB);
#pragma unroll
            for (int ni = 0; ni < 2; ++ni) {
                wmma::fragment<wmma::matrix_b, 16, 16, 16, __nv_bfloat16, wmma::row_major> vbh, vbm;
                wmma::load_matrix_sync(vbh, Vh + (ks*16)*AT_LDB + wn*32 + ni*16, AT_LDB);
                wmma::load_matrix_sync(vbm, Vm + (ks*16)*AT_LDB + wn*32 + ni*16, AT_LDB);
                wmma::mma_sync(oacc[ni], pah, vbh, oacc[ni]);
                wmma::mma_sync(oacc[ni], pah, vbm, oacc[ni]);
                wmma::mma_sync(oacc[ni], pam, vbh, oacc[ni]);
            }
        }
    }

    __syncthreads();
#pragma unroll
    for (int ni = 0; ni < 2; ++ni)
        wmma::store_matrix_sync(Ps + (wm*16)*AT_LDS + wn*32 + ni*16, oacc[ni],
                                AT_LDS, wmma::mem_row_major);
    __syncthreads();
#pragma unroll
    for (int i = 0; i < 4; ++i) {
        float rl = 1.0f / lrow[i];
        int n = nq0 + ty*4 + i;
        const float* pr = Ps + (ty*4+i)*AT_LDS + tx*4;
        size_t o = ((size_t)b*NN + n)*DD + h*DH + tx*4;
        __half2 haa[2], hbb[2];
#pragma unroll
        for (int jp = 0; jp < 2; ++jp) {
            float w0 = pr[jp*2+0]*rl, w1 = pr[jp*2+1]*rl;
            __half h0 = __float2half_rn(w0), h1 = __float2half_rn(w1);
            haa[jp] = __halves2half2(h0, h1);
            hbb[jp] = __halves2half2(__float2half_rn(w0 - __half2float(h0)),
                                     __float2half_rn(w1 - __half2float(h1)));
        }
        *(__half2*)(Aa + o)     = haa[0];
        *(__half2*)(Aa + o + 2) = haa[1];
        *(__half2*)(Ab + o)     = hbb[0];
        *(__half2*)(Ab + o + 2) = hbb[1];
    }
}

extern "C" void kernel_launch(void* const* d_in, const int* in_sizes, int n_in,
                              void* d_out, int out_size)
{
    (void)in_sizes; (void)n_in; (void)out_size;
    const float* X  = (const float*)d_in[0];
    const float* Wq = (const float*)d_in[1];
    const float* Wk = (const float*)d_in[2];
    const float* Wv = (const float*)d_in[3];
    const float* Wo = (const float*)d_in[4];
    const float* gq = (const float*)d_in[5];
    const float* bq = (const float*)d_in[6];
    const float* gk = (const float*)d_in[7];
    const float* bk = (const float*)d_in[8];
    float* out = (float*)d_out;

    float *Yq, *Yk, *Qp, *Kp, *S0, *Fi; int* ev;
    cudaGetSymbolAddress((void**)&Yq, g_Yq);
    cudaGetSymbolAddress((void**)&Yk, g_Yk);
    cudaGetSymbolAddress((void**)&Qp, g_Q);
    cudaGetSymbolAddress((void**)&Kp, g_K);
    cudaGetSymbolAddress((void**)&S0, g_S0);
    cudaGetSymbolAddress((void**)&Fi, g_Fi);
    cudaGetSymbolAddress((void**)&ev, g_ev);
    __half *hXa,*hXb,*hWqa,*hWqb,*hWka,*hWkb,*hWva,*hWvb,*hWoa,*hWob,*hAa,*hAb;
    cudaGetSymbolAddress((void**)&hXa, g_hXa);   cudaGetSymbolAddress((void**)&hXb, g_hXb);
    cudaGetSymbolAddress((void**)&hWqa, g_hWqa); cudaGetSymbolAddress((void**)&hWqb, g_hWqb);
    cudaGetSymbolAddress((void**)&hWka, g_hWka); cudaGetSymbolAddress((void**)&hWkb, g_hWkb);
    cudaGetSymbolAddress((void**)&hWva, g_hWva); cudaGetSymbolAddress((void**)&hWvb, g_hWvb);
    cudaGetSymbolAddress((void**)&hWoa, g_hWoa); cudaGetSymbolAddress((void**)&hWob, g_hWob);
    cudaGetSymbolAddress((void**)&hAa, g_hAa);   cudaGetSymbolAddress((void**)&hAb, g_hAb);
    __nv_bfloat16 *Qh,*Qm,*Kh,*Km,*Vh,*Vm;
    cudaGetSymbolAddress((void**)&Qh, g_Qh); cudaGetSymbolAddress((void**)&Qm, g_Qm);
    cudaGetSymbolAddress((void**)&Kh, g_Kh); cudaGetSymbolAddress((void**)&Km, g_Km);
    cudaGetSymbolAddress((void**)&Vh, g_Vh); cudaGetSymbolAddress((void**)&Vm, g_Vm);

    cudaFuncSetAttribute(attn_wmma_kernel, cudaFuncAttributeMaxDynamicSharedMemorySize, ATT2_SMEM);
    cudaFuncSetAttribute(gemm_h2_kernel, cudaFuncAttributeMaxDynamicSharedMemorySize, GH_SMEM);

    dim3 wgrid(32, 32);
    dim3 ggrid(DD/64, RR/128);

    conv2h_kernel<<<RR*DD/1024, 256>>>(X, hXa, hXb);                          // 0
    convW2h_kernel<<<wgrid, dim3(32,8)>>>(Wq, hWqa, hWqb);                    // 1
    convW2h_kernel<<<wgrid, dim3(32,8)>>>(Wk, hWka, hWkb);                    // 2
    convW2h_kernel<<<wgrid, dim3(32,8)>>>(Wv, hWva, hWvb);                    // 3
    convW2h_kernel<<<wgrid, dim3(32,8)>>>(Wo, hWoa, hWob);                    // 4
    gemm_h2_kernel<<<ggrid, 256, GH_SMEM>>>(hXa, hXb, hWqa, hWqb, Yq, nullptr, nullptr, 0); // 5 (profiled)
    gemm_h2_kernel<<<ggrid, 256, GH_SMEM>>>(hXa, hXb, hWka, hWkb, Yk, nullptr, nullptr, 0);
    gemm_h2_kernel<<<ggrid, 256, GH_SMEM>>>(hXa, hXb, hWva, hWvb, nullptr, Vh, Vm, 1);
    ln_scatter_kernel<<<RR, 256>>>(Yq, gq, bq, Qp, Qh, Qm);
    ln_scatter_kernel<<<RR, 256>>>(Yk, gk, bk, Kp, Kh, Km);
    s0_kernel<<<dim3(MM/64, NN/64, BB), 256>>>(Qp, Kp, S0);
    finit_kernel<<<dim3(MM/64, BB), 256>>>(S0, Fi);
    scan_kernel<<<BB, 1024>>>(S0, Fi, ev);
    attn_wmma_kernel<<<dim3(NN/64, HH, BB), 256, ATT2_SMEM>>>(Qh, Qm, Kh, Km, Vh, Vm, ev, hAa, hAb);
    gemm_h2_kernel<<<ggrid, 256, GH_SMEM>>>(hAa, hAb, hWoa, hWob, out, nullptr, nullptr, 0);
}